// round 3
// baseline (speedup 1.0000x reference)
#include <cuda_runtime.h>
#include <math.h>

// Problem constants (fixed shapes from reference setup_inputs)
#define Bb   4
#define Ls   4096
#define Dd   1024
#define Hh   64
#define ROWS (Bb*Ls)      // 16384
#define KCH  1024         // key chunk for split-K attention
#define NCH  (Ls/KCH)     // 4

// Scratch (device globals: no allocation allowed in kernel_launch)
__device__ float g_q  [ROWS*Hh];
__device__ float g_k  [ROWS*Hh];
__device__ float g_v  [ROWS*Hh];
__device__ float g_m  [NCH*ROWS];
__device__ float g_l  [NCH*ROWS];
__device__ float g_acc[(size_t)NCH*ROWS*Hh];

// ---------------------------------------------------------------------------
// Projection: C[16384,64] = X[16384,1024] * W[1024,64], for W in {Wq,Wk,Wv}
// BM=128, BN=64, BK=32, 256 threads, 8x4 register micro-tile per thread.
// ---------------------------------------------------------------------------
__global__ __launch_bounds__(256) void proj_kernel(
    const float* __restrict__ X,
    const float* __restrict__ Wq,
    const float* __restrict__ Wk,
    const float* __restrict__ Wv)
{
    __shared__ float Xs[128][36];   // padded to keep float4 stores aligned + spread banks
    __shared__ float Ws[32][64];

    const float* W   = (blockIdx.y == 0) ? Wq : (blockIdx.y == 1) ? Wk : Wv;
    float*       out = (blockIdx.y == 0) ? g_q : (blockIdx.y == 1) ? g_k : g_v;

    const int r0  = blockIdx.x * 128;
    const int tid = threadIdx.x;
    const int tx  = tid & 15;     // 16 col-groups of 4
    const int ty  = tid >> 4;     // 16 row-groups of 8

    float c[8][4];
#pragma unroll
    for (int r = 0; r < 8; r++)
#pragma unroll
        for (int n = 0; n < 4; n++) c[r][n] = 0.f;

    for (int k0 = 0; k0 < Dd; k0 += 32) {
        // Load X tile 128x32 (float4 along K)
#pragma unroll
        for (int i = 0; i < 4; i++) {
            int f   = tid + i * 256;          // 0..1023
            int row = f >> 3;
            int kk  = (f & 7) << 2;
            float4 v = *(const float4*)&X[(size_t)(r0 + row) * Dd + k0 + kk];
            *(float4*)&Xs[row][kk] = v;
        }
        // Load W tile 32x64
#pragma unroll
        for (int i = 0; i < 2; i++) {
            int f   = tid + i * 256;          // 0..511
            int kk  = f >> 4;
            int col = (f & 15) << 2;
            float4 v = *(const float4*)&W[(size_t)(k0 + kk) * Hh + col];
            *(float4*)&Ws[kk][col] = v;
        }
        __syncthreads();

#pragma unroll
        for (int kk = 0; kk < 32; kk++) {
            float4 b = *(const float4*)&Ws[kk][tx << 2];
#pragma unroll
            for (int r = 0; r < 8; r++) {
                float a = Xs[(ty << 3) + r][kk];     // warp-broadcast read
                c[r][0] += a * b.x;
                c[r][1] += a * b.y;
                c[r][2] += a * b.z;
                c[r][3] += a * b.w;
            }
        }
        __syncthreads();
    }

#pragma unroll
    for (int r = 0; r < 8; r++) {
        float4 v = make_float4(c[r][0], c[r][1], c[r][2], c[r][3]);
        *(float4*)&out[(size_t)(r0 + (ty << 3) + r) * Hh + (tx << 2)] = v;
    }
}

// ---------------------------------------------------------------------------
// Attention pass A: flash-attention partials per (qtile of 64, key-chunk, batch)
// 64 threads, 1 query row per thread. q (prescaled by 1/8) + acc in registers.
// Online softmax over 16-key groups. K/V tiles (64x64) staged in smem; all
// hot-loop smem reads are warp-uniform (broadcast, conflict-free).
// ---------------------------------------------------------------------------
__global__ __launch_bounds__(64) void attnA_kernel()
{
    __shared__ float4 Ks[64][16];
    __shared__ float4 Vs[64][16];

    const int qtile = blockIdx.x;
    const int c     = blockIdx.y;
    const int b     = blockIdx.z;
    const int q0    = qtile << 6;
    const int cbase = c << 10;
    if (cbase > q0) return;                    // chunk entirely above the diagonal

    const int tid  = threadIdx.x;
    const int grow = b * Ls + q0 + tid;        // global row of this thread's query

    float4 q4[16];
#pragma unroll
    for (int d = 0; d < 16; d++) {
        float4 v = *(const float4*)&g_q[(size_t)grow * Hh + (d << 2)];
        q4[d] = make_float4(v.x * 0.125f, v.y * 0.125f, v.z * 0.125f, v.w * 0.125f);
    }

    float4 acc[16];
#pragma unroll
    for (int d = 0; d < 16; d++) acc[d] = make_float4(0.f, 0.f, 0.f, 0.f);
    float m = -INFINITY, lsum = 0.f;

    const int cdiag  = q0 >> 10;
    const int ntiles = (c < cdiag) ? 16 : (((q0 - cbase) >> 6) + 1);
    const float* kb = g_k + (size_t)(b * Ls) * Hh;
    const float* vb = g_v + (size_t)(b * Ls) * Hh;

    for (int kt = 0; kt < ntiles; kt++) {
        const int kstart = cbase + (kt << 6);
        // Stage K/V tile (coalesced: threads 0..15 cover one 256B row segment)
#pragma unroll
        for (int i = 0; i < 16; i++) {
            int f   = tid + i * 64;            // 0..1023
            int row = f >> 4;
            int j   = f & 15;
            Ks[row][j] = *(const float4*)&kb[(size_t)(kstart + row) * Hh + (j << 2)];
            Vs[row][j] = *(const float4*)&vb[(size_t)(kstart + row) * Hh + (j << 2)];
        }
        __syncthreads();

        const bool diag = (kstart == q0);

#pragma unroll
        for (int g = 0; g < 4; g++) {
            float s[16];
#pragma unroll
            for (int j = 0; j < 16; j++) {
                const int key = (g << 4) + j;
                float sv = 0.f;
#pragma unroll
                for (int d = 0; d < 16; d++) {
                    float4 kv = Ks[key][d];    // broadcast
                    sv += q4[d].x * kv.x + q4[d].y * kv.y
                        + q4[d].z * kv.z + q4[d].w * kv.w;
                }
                s[j] = sv;
            }
            if (diag) {
#pragma unroll
                for (int j = 0; j < 16; j++)
                    if ((g << 4) + j > tid) s[j] = -INFINITY;
            }
            float tmax = s[0];
#pragma unroll
            for (int j = 1; j < 16; j++) tmax = fmaxf(tmax, s[j]);
            if (tmax == -INFINITY) continue;   // fully masked group

            const float mnew  = fmaxf(m, tmax);
            const float scale = __expf(m - mnew);   // exp(-inf)=0 on first group
            m = mnew;
            lsum *= scale;
#pragma unroll
            for (int d = 0; d < 16; d++) {
                acc[d].x *= scale; acc[d].y *= scale;
                acc[d].z *= scale; acc[d].w *= scale;
            }
#pragma unroll
            for (int j = 0; j < 16; j++) {
                const float p = __expf(s[j] - m);
                lsum += p;
                const int key = (g << 4) + j;
#pragma unroll
                for (int d = 0; d < 16; d++) {
                    float4 vv = Vs[key][d];    // broadcast
                    acc[d].x += p * vv.x; acc[d].y += p * vv.y;
                    acc[d].z += p * vv.z; acc[d].w += p * vv.w;
                }
            }
        }
        __syncthreads();
    }

    const int pidx = c * ROWS + grow;
    g_m[pidx] = m;
    g_l[pidx] = lsum;
#pragma unroll
    for (int d = 0; d < 16; d++)
        *(float4*)&g_acc[(size_t)pidx * Hh + (d << 2)] = acc[d];
}

// ---------------------------------------------------------------------------
// Combine: merge <=4 chunk partials per row. One thread per (row, float4-of-H).
// ---------------------------------------------------------------------------
__global__ __launch_bounds__(256) void combine_kernel(float* __restrict__ out)
{
    const int t   = blockIdx.x * blockDim.x + threadIdx.x;   // 0 .. ROWS*16-1
    const int row = t >> 4;
    const int d4  = t & 15;
    const int ll  = row & (Ls - 1);
    const int nch = (ll >> 10) + 1;

    float mc[NCH];
    mc[0] = g_m[row];
    float M = mc[0];
    for (int cc = 1; cc < nch; cc++) {
        mc[cc] = g_m[cc * ROWS + row];
        M = fmaxf(M, mc[cc]);
    }
    float  Lt = 0.f;
    float4 o  = make_float4(0.f, 0.f, 0.f, 0.f);
    for (int cc = 0; cc < nch; cc++) {
        const float w = __expf(mc[cc] - M);
        Lt += w * g_l[cc * ROWS + row];
        float4 a = *(const float4*)&g_acc[((size_t)cc * ROWS + row) * Hh + (d4 << 2)];
        o.x += w * a.x; o.y += w * a.y; o.z += w * a.z; o.w += w * a.w;
    }
    const float inv = 1.f / Lt;   // every row has >=1 valid key -> Lt > 0
    o.x *= inv; o.y *= inv; o.z *= inv; o.w *= inv;
    *(float4*)&out[(size_t)row * Hh + (d4 << 2)] = o;
}

// ---------------------------------------------------------------------------
extern "C" void kernel_launch(void* const* d_in, const int* in_sizes, int n_in,
                              void* d_out, int out_size)
{
    const float* x  = (const float*)d_in[0];
    const float* Wq = (const float*)d_in[1];
    const float* Wk = (const float*)d_in[2];
    const float* Wv = (const float*)d_in[3];
    float* out = (float*)d_out;

    dim3 pg(ROWS / 128, 3);
    proj_kernel<<<pg, 256>>>(x, Wq, Wk, Wv);

    dim3 ag(Ls / 64, NCH, Bb);
    attnA_kernel<<<ag, 64>>>();

    combine_kernel<<<(ROWS * 16) / 256, 256>>>(out);
}

// round 4
// speedup vs baseline: 1.5637x; 1.5637x over previous
#include <cuda_runtime.h>
#include <math.h>

// Problem constants (fixed shapes from reference setup_inputs)
#define Bb   4
#define Ls   4096
#define Dd   1024
#define Hh   64
#define ROWS (Bb*Ls)      // 16384
#define KCH  256          // key chunk for split-K attention (finer -> multi-wave balance)
#define NCH  (Ls/KCH)     // 16

// Scratch (device globals: no allocation allowed in kernel_launch)
__device__ float g_q  [ROWS*Hh];
__device__ float g_k  [ROWS*Hh];
__device__ float g_v  [ROWS*Hh];
__device__ float g_m  [NCH*ROWS];
__device__ float g_l  [NCH*ROWS];
__device__ float g_acc[(size_t)NCH*ROWS*Hh];   // 64 MB static scratch

// ---------------------------------------------------------------------------
// Projection: C[16384,64] = X[16384,1024] * W[1024,64], for W in {Wq,Wk,Wv}
// BM=128, BN=64, BK=32, 128 threads, 8x8 register micro-tile per thread.
// 64 FFMA : 10 LDS per k-step -> ~86% fma ceiling, ILP=64.
// ---------------------------------------------------------------------------
__global__ __launch_bounds__(128) void proj_kernel(
    const float* __restrict__ X,
    const float* __restrict__ Wq,
    const float* __restrict__ Wk,
    const float* __restrict__ Wv)
{
    __shared__ float Xs[128][33];   // pad 33: ty-row-group stride 264 = 8 mod 32 -> conflict-free
    __shared__ float Ws[32][64];

    const float* W   = (blockIdx.y == 0) ? Wq : (blockIdx.y == 1) ? Wk : Wv;
    float*       out = (blockIdx.y == 0) ? g_q : (blockIdx.y == 1) ? g_k : g_v;

    const int r0  = blockIdx.x * 128;
    const int tid = threadIdx.x;
    const int tx  = tid & 7;      // 8 col-groups of 8
    const int ty  = tid >> 3;     // 16 row-groups of 8

    float c[8][8];
#pragma unroll
    for (int r = 0; r < 8; r++)
#pragma unroll
        for (int n = 0; n < 8; n++) c[r][n] = 0.f;

    for (int k0 = 0; k0 < Dd; k0 += 32) {
        // Load X tile 128x32 (float4 gmem loads, scalar smem stores due to pad 33)
#pragma unroll
        for (int i = 0; i < 8; i++) {
            int f   = tid + i * 128;          // 0..1023
            int row = f >> 3;
            int kk  = (f & 7) << 2;
            float4 v = *(const float4*)&X[(size_t)(r0 + row) * Dd + k0 + kk];
            Xs[row][kk + 0] = v.x;
            Xs[row][kk + 1] = v.y;
            Xs[row][kk + 2] = v.z;
            Xs[row][kk + 3] = v.w;
        }
        // Load W tile 32x64
#pragma unroll
        for (int i = 0; i < 4; i++) {
            int f   = tid + i * 128;          // 0..511
            int kk  = f >> 4;
            int col = (f & 15) << 2;
            float4 v = *(const float4*)&W[(size_t)(k0 + kk) * Hh + col];
            *(float4*)&Ws[kk][col] = v;
        }
        __syncthreads();

#pragma unroll
        for (int kk = 0; kk < 32; kk++) {
            float4 b0 = *(const float4*)&Ws[kk][(tx << 3)];
            float4 b1 = *(const float4*)&Ws[kk][(tx << 3) + 4];
            float a[8];
#pragma unroll
            for (int r = 0; r < 8; r++) a[r] = Xs[(ty << 3) + r][kk];  // broadcast
#pragma unroll
            for (int r = 0; r < 8; r++) {
                c[r][0] = fmaf(a[r], b0.x, c[r][0]);
                c[r][1] = fmaf(a[r], b0.y, c[r][1]);
                c[r][2] = fmaf(a[r], b0.z, c[r][2]);
                c[r][3] = fmaf(a[r], b0.w, c[r][3]);
                c[r][4] = fmaf(a[r], b1.x, c[r][4]);
                c[r][5] = fmaf(a[r], b1.y, c[r][5]);
                c[r][6] = fmaf(a[r], b1.z, c[r][6]);
                c[r][7] = fmaf(a[r], b1.w, c[r][7]);
            }
        }
        __syncthreads();
    }

#pragma unroll
    for (int r = 0; r < 8; r++) {
        float4 v0 = make_float4(c[r][0], c[r][1], c[r][2], c[r][3]);
        float4 v1 = make_float4(c[r][4], c[r][5], c[r][6], c[r][7]);
        float* op = &out[(size_t)(r0 + (ty << 3) + r) * Hh + (tx << 3)];
        *(float4*)op       = v0;
        *(float4*)(op + 4) = v1;
    }
}

// ---------------------------------------------------------------------------
// Attention pass A: flash-attention partials per (qtile of 64, key-chunk of 256, batch)
// 64 threads, 1 query row per thread. q (prescaled by 1/8) + acc in registers.
// Score dot uses float4 partial sums (ILP=4). Online softmax over 16-key groups.
// ---------------------------------------------------------------------------
__global__ __launch_bounds__(64) void attnA_kernel()
{
    __shared__ float4 Ks[64][16];
    __shared__ float4 Vs[64][16];

    const int qtile = blockIdx.x;
    const int c     = blockIdx.y;
    const int b     = blockIdx.z;
    const int q0    = qtile << 6;
    const int cbase = c << 8;                  // 256-key chunks
    if (cbase > q0) return;                    // chunk entirely above the diagonal

    const int tid  = threadIdx.x;
    const int grow = b * Ls + q0 + tid;        // global row of this thread's query

    float4 q4[16];
#pragma unroll
    for (int d = 0; d < 16; d++) {
        float4 v = *(const float4*)&g_q[(size_t)grow * Hh + (d << 2)];
        q4[d] = make_float4(v.x * 0.125f, v.y * 0.125f, v.z * 0.125f, v.w * 0.125f);
    }

    float4 acc[16];
#pragma unroll
    for (int d = 0; d < 16; d++) acc[d] = make_float4(0.f, 0.f, 0.f, 0.f);
    float m = -INFINITY, lsum = 0.f;

    const int cdiag  = q0 >> 8;
    const int ntiles = (c < cdiag) ? 4 : (((q0 - cbase) >> 6) + 1);
    const float* kb = g_k + (size_t)(b * Ls) * Hh;
    const float* vb = g_v + (size_t)(b * Ls) * Hh;

    for (int kt = 0; kt < ntiles; kt++) {
        const int kstart = cbase + (kt << 6);
        // Stage K/V tile (coalesced)
#pragma unroll
        for (int i = 0; i < 16; i++) {
            int f   = tid + i * 64;            // 0..1023
            int row = f >> 4;
            int j   = f & 15;
            Ks[row][j] = *(const float4*)&kb[(size_t)(kstart + row) * Hh + (j << 2)];
            Vs[row][j] = *(const float4*)&vb[(size_t)(kstart + row) * Hh + (j << 2)];
        }
        __syncthreads();

        const bool diag = (kstart == q0);

#pragma unroll
        for (int g = 0; g < 4; g++) {
            float s[16];
#pragma unroll
            for (int j = 0; j < 16; j++) {
                const int key = (g << 4) + j;
                float4 sv = make_float4(0.f, 0.f, 0.f, 0.f);   // 4 independent chains
#pragma unroll
                for (int d = 0; d < 16; d++) {
                    float4 kv = Ks[key][d];    // broadcast
                    sv.x = fmaf(q4[d].x, kv.x, sv.x);
                    sv.y = fmaf(q4[d].y, kv.y, sv.y);
                    sv.z = fmaf(q4[d].z, kv.z, sv.z);
                    sv.w = fmaf(q4[d].w, kv.w, sv.w);
                }
                s[j] = (sv.x + sv.y) + (sv.z + sv.w);
            }
            if (diag) {
#pragma unroll
                for (int j = 0; j < 16; j++)
                    if ((g << 4) + j > tid) s[j] = -INFINITY;
            }
            float tmax = s[0];
#pragma unroll
            for (int j = 1; j < 16; j++) tmax = fmaxf(tmax, s[j]);
            if (tmax == -INFINITY) continue;   // fully masked group

            const float mnew  = fmaxf(m, tmax);
            const float scale = __expf(m - mnew);   // exp(-inf)=0 on first group
            m = mnew;
            lsum *= scale;
#pragma unroll
            for (int d = 0; d < 16; d++) {
                acc[d].x *= scale; acc[d].y *= scale;
                acc[d].z *= scale; acc[d].w *= scale;
            }
#pragma unroll
            for (int j = 0; j < 16; j++) {
                const float p = __expf(s[j] - m);
                lsum += p;
                const int key = (g << 4) + j;
#pragma unroll
                for (int d = 0; d < 16; d++) {
                    float4 vv = Vs[key][d];    // broadcast
                    acc[d].x = fmaf(p, vv.x, acc[d].x);
                    acc[d].y = fmaf(p, vv.y, acc[d].y);
                    acc[d].z = fmaf(p, vv.z, acc[d].z);
                    acc[d].w = fmaf(p, vv.w, acc[d].w);
                }
            }
        }
        __syncthreads();
    }

    const int pidx = c * ROWS + grow;
    g_m[pidx] = m;
    g_l[pidx] = lsum;
#pragma unroll
    for (int d = 0; d < 16; d++)
        *(float4*)&g_acc[(size_t)pidx * Hh + (d << 2)] = acc[d];
}

// ---------------------------------------------------------------------------
// Combine: merge <=16 chunk partials per row. One thread per (row, float4-of-H).
// Two passes over g_m (L2-resident) to avoid a local array.
// ---------------------------------------------------------------------------
__global__ __launch_bounds__(256) void combine_kernel(float* __restrict__ out)
{
    const int t   = blockIdx.x * blockDim.x + threadIdx.x;   // 0 .. ROWS*16-1
    const int row = t >> 4;
    const int d4  = t & 15;
    const int ll  = row & (Ls - 1);
    const int nch = (ll >> 8) + 1;          // active 256-key chunks for this row

    float M = -INFINITY;
#pragma unroll 4
    for (int cc = 0; cc < nch; cc++)
        M = fmaxf(M, g_m[cc * ROWS + row]);

    float  Lt = 0.f;
    float4 o  = make_float4(0.f, 0.f, 0.f, 0.f);
#pragma unroll 4
    for (int cc = 0; cc < nch; cc++) {
        const float w = __expf(g_m[cc * ROWS + row] - M);
        Lt += w * g_l[cc * ROWS + row];
        float4 a = *(const float4*)&g_acc[((size_t)cc * ROWS + row) * Hh + (d4 << 2)];
        o.x = fmaf(w, a.x, o.x); o.y = fmaf(w, a.y, o.y);
        o.z = fmaf(w, a.z, o.z); o.w = fmaf(w, a.w, o.w);
    }
    const float inv = 1.f / Lt;   // every row has >=1 valid key -> Lt > 0
    o.x *= inv; o.y *= inv; o.z *= inv; o.w *= inv;
    *(float4*)&out[(size_t)row * Hh + (d4 << 2)] = o;
}

// ---------------------------------------------------------------------------
extern "C" void kernel_launch(void* const* d_in, const int* in_sizes, int n_in,
                              void* d_out, int out_size)
{
    const float* x  = (const float*)d_in[0];
    const float* Wq = (const float*)d_in[1];
    const float* Wk = (const float*)d_in[2];
    const float* Wv = (const float*)d_in[3];
    float* out = (float*)d_out;

    dim3 pg(ROWS / 128, 3);
    proj_kernel<<<pg, 128>>>(x, Wq, Wk, Wv);

    dim3 ag(Ls / 64, NCH, Bb);
    attnA_kernel<<<ag, 64>>>();

    combine_kernel<<<(ROWS * 16) / 256, 256>>>(out);
}

// round 6
// speedup vs baseline: 2.1169x; 1.3538x over previous
#include <cuda_runtime.h>
#include <math.h>

// Problem constants (fixed shapes from reference setup_inputs)
#define Bb   4
#define Ls   4096
#define Dd   1024
#define Hh   64
#define ROWS (Bb*Ls)      // 16384
#define KCH  256          // key chunk for split-K attention
#define NCH  (Ls/KCH)     // 16

typedef unsigned long long u64;

// Scratch (device globals: no allocation allowed in kernel_launch)
__device__ float g_q  [ROWS*Hh];
__device__ float g_k  [ROWS*Hh];
__device__ float g_v  [ROWS*Hh];
__device__ float g_m  [NCH*ROWS];
__device__ float g_l  [NCH*ROWS];
__device__ float g_acc[(size_t)NCH*ROWS*Hh];

// ---- packed f32x2 helpers (sm_103a: ptxas never auto-emits FFMA2) ----------
__device__ __forceinline__ void fma2(u64& d, u64 a, u64 b) {
    asm("fma.rn.f32x2 %0, %1, %2, %0;" : "+l"(d) : "l"(a), "l"(b));
}
__device__ __forceinline__ void mul2(u64& d, u64 a, u64 b) {
    asm("mul.rn.f32x2 %0, %1, %2;" : "=l"(d) : "l"(a), "l"(b));
}
__device__ __forceinline__ u64 pack2(float x, float y) {
    u64 r; asm("mov.b64 %0, {%1, %2};" : "=l"(r) : "f"(x), "f"(y)); return r;
}
__device__ __forceinline__ void unpack2(u64 v, float& x, float& y) {
    asm("mov.b64 {%0, %1}, %2;" : "=f"(x), "=f"(y) : "l"(v));
}

// ---------------------------------------------------------------------------
// Projection: C[16384,64] = X[16384,1024] * W[1024,64], for W in {Wq,Wk,Wv}
// BM=128, BN=64, BK=32, 128 threads, 8x8 micro-tile held as 8x4 packed f32x2.
// Inner k-step: 32 FFMA2 + 8 pack + 10 LDS.
// ---------------------------------------------------------------------------
__global__ __launch_bounds__(128) void proj_kernel(
    const float* __restrict__ X,
    const float* __restrict__ Wq,
    const float* __restrict__ Wk,
    const float* __restrict__ Wv)
{
    __shared__ float Xs[128][33];   // pad 33: conflict-free broadcast reads
    __shared__ float Ws[32][64];

    const float* W   = (blockIdx.y == 0) ? Wq : (blockIdx.y == 1) ? Wk : Wv;
    float*       out = (blockIdx.y == 0) ? g_q : (blockIdx.y == 1) ? g_k : g_v;

    const int r0  = blockIdx.x * 128;
    const int tid = threadIdx.x;
    const int tx  = tid & 7;      // 8 col-groups of 8
    const int ty  = tid >> 3;     // 16 row-groups of 8

    u64 cp[8][4];
#pragma unroll
    for (int r = 0; r < 8; r++)
#pragma unroll
        for (int n = 0; n < 4; n++) cp[r][n] = 0ULL;   // (0.0f,0.0f)

    for (int k0 = 0; k0 < Dd; k0 += 32) {
#pragma unroll
        for (int i = 0; i < 8; i++) {
            int f   = tid + i * 128;          // 0..1023
            int row = f >> 3;
            int kk  = (f & 7) << 2;
            float4 v = *(const float4*)&X[(size_t)(r0 + row) * Dd + k0 + kk];
            Xs[row][kk + 0] = v.x;
            Xs[row][kk + 1] = v.y;
            Xs[row][kk + 2] = v.z;
            Xs[row][kk + 3] = v.w;
        }
#pragma unroll
        for (int i = 0; i < 4; i++) {
            int f   = tid + i * 128;          // 0..511
            int kk  = f >> 4;
            int col = (f & 15) << 2;
            float4 v = *(const float4*)&W[(size_t)(k0 + kk) * Hh + col];
            *(float4*)&Ws[kk][col] = v;
        }
        __syncthreads();

#pragma unroll
        for (int kk = 0; kk < 32; kk++) {
            const ulonglong2* wr = (const ulonglong2*)&Ws[kk][tx << 3];
            ulonglong2 w0 = wr[0];   // packed (b0,b1),(b2,b3)
            ulonglong2 w1 = wr[1];   // packed (b4,b5),(b6,b7)
#pragma unroll
            for (int r = 0; r < 8; r++) {
                float a = Xs[(ty << 3) + r][kk];     // broadcast
                u64 ap = pack2(a, a);
                fma2(cp[r][0], ap, w0.x);
                fma2(cp[r][1], ap, w0.y);
                fma2(cp[r][2], ap, w1.x);
                fma2(cp[r][3], ap, w1.y);
            }
        }
        __syncthreads();
    }

#pragma unroll
    for (int r = 0; r < 8; r++) {
        float* op = &out[(size_t)(r0 + (ty << 3) + r) * Hh + (tx << 3)];
        *(ulonglong2*)op       = make_ulonglong2(cp[r][0], cp[r][1]);
        *(ulonglong2*)(op + 4) = make_ulonglong2(cp[r][2], cp[r][3]);
    }
}

// ---------------------------------------------------------------------------
// Attention pass A: flash partials per (qtile 64, key-chunk 256, batch).
// 64 threads, 1 query row per thread. q + acc packed f32x2 in registers.
// Per key: 32 FFMA2 (QK) + 32 FFMA2 (PV) + 32 LDS.128-lane.
// ---------------------------------------------------------------------------
__global__ __launch_bounds__(64) void attnA_kernel()
{
    __shared__ float4 Ks[64][16];
    __shared__ float4 Vs[64][16];

    const int qtile = blockIdx.x;
    const int c     = blockIdx.y;
    const int b     = blockIdx.z;
    const int q0    = qtile << 6;
    const int cbase = c << 8;
    if (cbase > q0) return;

    const int tid  = threadIdx.x;
    const int grow = b * Ls + q0 + tid;

    // load + prescale q, packed
    u64 qp[32];
    {
        const u64 sc = pack2(0.125f, 0.125f);
        const ulonglong2* qr = (const ulonglong2*)&g_q[(size_t)grow * Hh];
#pragma unroll
        for (int d = 0; d < 16; d++) {
            ulonglong2 v = qr[d];
            mul2(qp[2*d],   v.x, sc);
            mul2(qp[2*d+1], v.y, sc);
        }
    }

    u64 accp[32];
#pragma unroll
    for (int i = 0; i < 32; i++) accp[i] = 0ULL;
    float m = -INFINITY, lsum = 0.f;

    const int cdiag  = q0 >> 8;
    const int ntiles = (c < cdiag) ? 4 : (((q0 - cbase) >> 6) + 1);
    const float* kb = g_k + (size_t)(b * Ls) * Hh;
    const float* vb = g_v + (size_t)(b * Ls) * Hh;

    for (int kt = 0; kt < ntiles; kt++) {
        const int kstart = cbase + (kt << 6);
#pragma unroll
        for (int i = 0; i < 16; i++) {
            int f   = tid + i * 64;
            int row = f >> 4;
            int j   = f & 15;
            Ks[row][j] = *(const float4*)&kb[(size_t)(kstart + row) * Hh + (j << 2)];
            Vs[row][j] = *(const float4*)&vb[(size_t)(kstart + row) * Hh + (j << 2)];
        }
        __syncthreads();

        const bool diag = (kstart == q0);

#pragma unroll
        for (int g = 0; g < 4; g++) {
            float s[16];
#pragma unroll
            for (int j = 0; j < 16; j++) {
                const int key = (g << 4) + j;
                const ulonglong2* kr = (const ulonglong2*)&Ks[key][0];
                u64 s0 = 0ULL, s1 = 0ULL;        // 4 independent fp32 chains
#pragma unroll
                for (int d = 0; d < 16; d++) {
                    ulonglong2 kv = kr[d];       // broadcast 16B
                    fma2(s0, qp[2*d],   kv.x);
                    fma2(s1, qp[2*d+1], kv.y);
                }
                float a0, a1, a2, a3;
                unpack2(s0, a0, a1);
                unpack2(s1, a2, a3);
                s[j] = (a0 + a1) + (a2 + a3);
            }
            if (diag) {
#pragma unroll
                for (int j = 0; j < 16; j++)
                    if ((g << 4) + j > tid) s[j] = -INFINITY;
            }
            float tmax = s[0];
#pragma unroll
            for (int j = 1; j < 16; j++) tmax = fmaxf(tmax, s[j]);
            if (tmax == -INFINITY) continue;

            const float mnew  = fmaxf(m, tmax);
            const float scale = __expf(m - mnew);
            m = mnew;
            lsum *= scale;
            {
                const u64 ss = pack2(scale, scale);
#pragma unroll
                for (int i = 0; i < 32; i++) mul2(accp[i], accp[i], ss);
            }
#pragma unroll
            for (int j = 0; j < 16; j++) {
                const float p = __expf(s[j] - m);
                lsum += p;
                const u64 pp = pack2(p, p);
                const int key = (g << 4) + j;
                const ulonglong2* vr = (const ulonglong2*)&Vs[key][0];
#pragma unroll
                for (int d = 0; d < 16; d++) {
                    ulonglong2 vv = vr[d];       // broadcast 16B
                    fma2(accp[2*d],   pp, vv.x);
                    fma2(accp[2*d+1], pp, vv.y);
                }
            }
        }
        __syncthreads();
    }

    const int pidx = c * ROWS + grow;
    g_m[pidx] = m;
    g_l[pidx] = lsum;
    ulonglong2* ar = (ulonglong2*)&g_acc[(size_t)pidx * Hh];
#pragma unroll
    for (int d = 0; d < 16; d++)
        ar[d] = make_ulonglong2(accp[2*d], accp[2*d+1]);
}

// ---------------------------------------------------------------------------
// Combine: merge <=16 chunk partials per row. One thread per (row, float4-of-H).
// ---------------------------------------------------------------------------
__global__ __launch_bounds__(256) void combine_kernel(float* __restrict__ out)
{
    const int t   = blockIdx.x * blockDim.x + threadIdx.x;
    const int row = t >> 4;
    const int d4  = t & 15;
    const int ll  = row & (Ls - 1);
    const int nch = (ll >> 8) + 1;

    float M = -INFINITY;
#pragma unroll 4
    for (int cc = 0; cc < nch; cc++)
        M = fmaxf(M, g_m[cc * ROWS + row]);

    float  Lt = 0.f;
    float4 o  = make_float4(0.f, 0.f, 0.f, 0.f);
#pragma unroll 4
    for (int cc = 0; cc < nch; cc++) {
        const float w = __expf(g_m[cc * ROWS + row] - M);
        Lt += w * g_l[cc * ROWS + row];
        float4 a = *(const float4*)&g_acc[((size_t)cc * ROWS + row) * Hh + (d4 << 2)];
        o.x = fmaf(w, a.x, o.x); o.y = fmaf(w, a.y, o.y);
        o.z = fmaf(w, a.z, o.z); o.w = fmaf(w, a.w, o.w);
    }
    const float inv = 1.f / Lt;
    o.x *= inv; o.y *= inv; o.z *= inv; o.w *= inv;
    *(float4*)&out[(size_t)row * Hh + (d4 << 2)] = o;
}

// ---------------------------------------------------------------------------
extern "C" void kernel_launch(void* const* d_in, const int* in_sizes, int n_in,
                              void* d_out, int out_size)
{
    const float* x  = (const float*)d_in[0];
    const float* Wq = (const float*)d_in[1];
    const float* Wk = (const float*)d_in[2];
    const float* Wv = (const float*)d_in[3];
    float* out = (float*)d_out;

    dim3 pg(ROWS / 128, 3);
    proj_kernel<<<pg, 128>>>(x, Wq, Wk, Wv);

    dim3 ag(Ls / 64, NCH, Bb);
    attnA_kernel<<<ag, 64>>>();

    combine_kernel<<<(ROWS * 16) / 256, 256>>>(out);
}

// round 7
// speedup vs baseline: 2.2137x; 1.0457x over previous
#include <cuda_runtime.h>
#include <math.h>

#define Bb   4
#define Ls   4096
#define Dd   1024
#define Hh   64
#define ROWS (Bb*Ls)      // 16384
#define KCH  256
#define NCH  (Ls/KCH)     // 16

typedef unsigned long long u64;

__device__ float g_q  [ROWS*Hh];
__device__ float g_k  [ROWS*Hh];
__device__ float g_v  [ROWS*Hh];
__device__ float g_m  [NCH*ROWS];
__device__ float g_l  [NCH*ROWS];
__device__ float g_acc[(size_t)NCH*ROWS*Hh];

// ---- packed f32x2 helpers ---------------------------------------------------
__device__ __forceinline__ void fma2(u64& d, u64 a, u64 b) {
    asm("fma.rn.f32x2 %0, %1, %2, %0;" : "+l"(d) : "l"(a), "l"(b));
}
__device__ __forceinline__ void mul2(u64& d, u64 a, u64 b) {
    asm("mul.rn.f32x2 %0, %1, %2;" : "=l"(d) : "l"(a), "l"(b));
}
__device__ __forceinline__ u64 pack2(float x, float y) {
    u64 r; asm("mov.b64 %0, {%1, %2};" : "=l"(r) : "f"(x), "f"(y)); return r;
}
__device__ __forceinline__ void unpack2(u64 v, float& x, float& y) {
    asm("mov.b64 {%0, %1}, %2;" : "=f"(x), "=f"(y) : "l"(v));
}

// ---------------------------------------------------------------------------
// Fused projection: C[16384,192] = X[16384,1024] * [Wq|Wk|Wv]
// BM=64, BN=192, BK=32, 128 threads, micro-tile 8 rows x 12 cols (6 u64 acc).
// X staged TRANSPOSED (XsT[kk][row]) with 8-row XOR swizzle -> a-operand reads
// are 2 full-width conflict-free LDS.128 per k-step (was 8 scalar broadcasts).
// ---------------------------------------------------------------------------
__global__ __launch_bounds__(128) void proj_kernel(
    const float* __restrict__ X,
    const float* __restrict__ Wq,
    const float* __restrict__ Wk,
    const float* __restrict__ Wv)
{
    __shared__ float XsT[32*64];     // [kk][row], row-block XOR swizzled
    __shared__ float Ws [32*192];    // [kk][col 0..191]

    const int r0  = blockIdx.x * 64;
    const int tid = threadIdx.x;
    const int tx  = tid & 15;        // 16 col-groups of 12
    const int ty  = tid >> 4;        // 8 row-groups of 8

    u64 c[8][6];
#pragma unroll
    for (int r = 0; r < 8; r++)
#pragma unroll
        for (int n = 0; n < 6; n++) c[r][n] = 0ULL;

    for (int k0 = 0; k0 < Dd; k0 += 32) {
        // Stage X tile 64x32 transposed+swizzled: phys = kk*64 + ((row>>3)^(kk&7))*8 + (row&7)
#pragma unroll
        for (int i = 0; i < 4; i++) {
            int f   = tid + i * 128;          // 0..511
            int row = f >> 3;
            int kc  = (f & 7) << 2;
            float4 v = *(const float4*)&X[(size_t)(r0 + row) * Dd + k0 + kc];
            float vv[4] = {v.x, v.y, v.z, v.w};
#pragma unroll
            for (int cc = 0; cc < 4; cc++) {
                int kk = kc + cc;
                XsT[kk * 64 + (((row >> 3) ^ (kk & 7)) << 3) + (row & 7)] = vv[cc];
            }
        }
        // Stage W tile 32x192 (cols 0-63:Wq, 64-127:Wk, 128-191:Wv)
#pragma unroll
        for (int i = 0; i < 12; i++) {
            int f   = tid + i * 128;          // 0..1535
            int kk  = f / 48;
            int col = (f % 48) << 2;
            const float* Wm = (col < 64) ? Wq : (col < 128) ? Wk : Wv;
            float4 v = *(const float4*)&Wm[(size_t)(k0 + kk) * Hh + (col & 63)];
            *(float4*)&Ws[kk * 192 + col] = v;
        }
        __syncthreads();

#pragma unroll
        for (int kk = 0; kk < 32; kk++) {
            const u64* wrow = (const u64*)&Ws[kk * 192 + tx * 12];
            u64 w0 = wrow[0], w1 = wrow[1], w2 = wrow[2];
            u64 w3 = wrow[3], w4 = wrow[4], w5 = wrow[5];
            const float* ab = &XsT[kk * 64 + (((ty ^ (kk & 7))) << 3)];
            float4 a0 = *(const float4*)ab;
            float4 a1 = *(const float4*)(ab + 4);
            float av[8] = {a0.x, a0.y, a0.z, a0.w, a1.x, a1.y, a1.z, a1.w};
#pragma unroll
            for (int r = 0; r < 8; r++) {
                u64 ap = pack2(av[r], av[r]);
                fma2(c[r][0], ap, w0);
                fma2(c[r][1], ap, w1);
                fma2(c[r][2], ap, w2);
                fma2(c[r][3], ap, w3);
                fma2(c[r][4], ap, w4);
                fma2(c[r][5], ap, w5);
            }
        }
        __syncthreads();
    }

    // Write out: col pair (2n) -> matrix (col>>6), local col (col&63)
#pragma unroll
    for (int r = 0; r < 8; r++) {
        const size_t row = (size_t)(r0 + (ty << 3) + r);
#pragma unroll
        for (int n = 0; n < 6; n++) {
            int col = tx * 12 + 2 * n;
            float* dst = (col < 64) ? g_q : (col < 128) ? g_k : g_v;
            *(u64*)&dst[row * Hh + (col & 63)] = c[r][n];
        }
    }
}

// ---------------------------------------------------------------------------
// Attention pass A: qtile 64, key-chunk 256, batch. 64 threads.
// Thread (u = tid>>1, h = tid&1) owns queries {2u, 2u+1} restricted to d-half h.
// Even/odd lanes read different 16B chunks of each K/V row -> 16 smem
// wavefronts per key per warp (was 32). Half-dots combined via shfl.xor(1).
// K/V smem rows: 34 u64 (pad 2); float4 j stored at u64 idx 4*(j&7) + 2*(j>>3),
// so thread h reads chunks at u64 idx 4*i + 2*h, i=0..7.
// ---------------------------------------------------------------------------
__global__ __launch_bounds__(64) void attnA_kernel()
{
    __shared__ u64 KsU[64 * 34];
    __shared__ u64 VsU[64 * 34];

    const int qtile = blockIdx.x;
    const int c     = blockIdx.y;
    const int b     = blockIdx.z;
    const int q0    = qtile << 6;
    const int cbase = c << 8;
    if (cbase > q0) return;

    const int tid = threadIdx.x;
    const int u   = tid >> 1;
    const int h   = tid & 1;
    const int qA  = (u << 1);            // local query ids
    const int qB  = qA + 1;
    const int growA = b * Ls + q0 + qA;
    const int growB = growA + 1;

    // q halves, prescaled by 1/8
    u64 qpA[16], qpB[16];
    {
        const u64 sc = pack2(0.125f, 0.125f);
        const ulonglong2* pa = (const ulonglong2*)&g_q[(size_t)growA * Hh + h * 32];
        const ulonglong2* pb = (const ulonglong2*)&g_q[(size_t)growB * Hh + h * 32];
#pragma unroll
        for (int i = 0; i < 8; i++) {
            ulonglong2 va = pa[i], vb = pb[i];
            mul2(qpA[2*i],   va.x, sc); mul2(qpA[2*i+1], va.y, sc);
            mul2(qpB[2*i],   vb.x, sc); mul2(qpB[2*i+1], vb.y, sc);
        }
    }

    u64 accA[16], accB[16];
#pragma unroll
    for (int i = 0; i < 16; i++) { accA[i] = 0ULL; accB[i] = 0ULL; }
    float mA = -1e30f, mB = -1e30f, lA = 0.f, lB = 0.f;

    const int cdiag  = q0 >> 8;
    const int ntiles = (c < cdiag) ? 4 : (((q0 - cbase) >> 6) + 1);
    const float* kb = g_k + (size_t)(b * Ls) * Hh;
    const float* vb = g_v + (size_t)(b * Ls) * Hh;

    for (int kt = 0; kt < ntiles; kt++) {
        const int kstart = cbase + (kt << 6);
        // Stage K/V 64x64 into chunked layout
#pragma unroll
        for (int i = 0; i < 16; i++) {
            int f   = tid + i * 64;
            int row = f >> 4;
            int j   = f & 15;
            int di  = row * 34 + ((j & 7) << 2) + ((j >> 3) << 1);
            const float4 kv4 = *(const float4*)&kb[(size_t)(kstart + row) * Hh + (j << 2)];
            const float4 vv4 = *(const float4*)&vb[(size_t)(kstart + row) * Hh + (j << 2)];
            *(float4*)&KsU[di] = kv4;
            *(float4*)&VsU[di] = vv4;
        }
        __syncthreads();

        const bool diag = (kstart == q0);

#pragma unroll
        for (int g = 0; g < 4; g++) {
            float sA[16], sB[16];
#pragma unroll
            for (int j = 0; j < 16; j++) {
                const int key = (g << 4) + j;
                const u64* kr = &KsU[key * 34 + (h << 1)];
                u64 a0 = 0ULL, a1 = 0ULL, b0 = 0ULL, b1 = 0ULL;
#pragma unroll
                for (int i = 0; i < 8; i++) {
                    ulonglong2 kv = *(const ulonglong2*)(kr + (i << 2));
                    fma2(a0, qpA[2*i],   kv.x);
                    fma2(a1, qpA[2*i+1], kv.y);
                    fma2(b0, qpB[2*i],   kv.x);
                    fma2(b1, qpB[2*i+1], kv.y);
                }
                float x0, x1, x2, x3, y0, y1, y2, y3;
                unpack2(a0, x0, x1); unpack2(a1, x2, x3);
                unpack2(b0, y0, y1); unpack2(b1, y2, y3);
                float ra = (x0 + x1) + (x2 + x3);
                float rb = (y0 + y1) + (y2 + y3);
                sA[j] = ra + __shfl_xor_sync(0xffffffffu, ra, 1);
                sB[j] = rb + __shfl_xor_sync(0xffffffffu, rb, 1);
            }
            if (diag) {
#pragma unroll
                for (int j = 0; j < 16; j++) {
                    const int key = (g << 4) + j;
                    if (key > qA) sA[j] = -INFINITY;
                    if (key > qB) sB[j] = -INFINITY;
                }
            }
            float tA = sA[0], tB = sB[0];
#pragma unroll
            for (int j = 1; j < 16; j++) { tA = fmaxf(tA, sA[j]); tB = fmaxf(tB, sB[j]); }
            if (fmaxf(tA, tB) == -INFINITY) continue;   // both queries fully masked

            if (tA > mA) {
                const float s = __expf(mA - tA);
                mA = tA; lA *= s;
                const u64 ss = pack2(s, s);
#pragma unroll
                for (int i = 0; i < 16; i++) mul2(accA[i], accA[i], ss);
            }
            if (tB > mB) {
                const float s = __expf(mB - tB);
                mB = tB; lB *= s;
                const u64 ss = pack2(s, s);
#pragma unroll
                for (int i = 0; i < 16; i++) mul2(accB[i], accB[i], ss);
            }
#pragma unroll
            for (int j = 0; j < 16; j++) {
                const int key = (g << 4) + j;
                const float pA = __expf(sA[j] - mA);   // exp(-inf - m) = 0 for masked
                const float pB = __expf(sB[j] - mB);
                lA += pA; lB += pB;
                const u64 ppA = pack2(pA, pA);
                const u64 ppB = pack2(pB, pB);
                const u64* vr = &VsU[key * 34 + (h << 1)];
#pragma unroll
                for (int i = 0; i < 8; i++) {
                    ulonglong2 vv = *(const ulonglong2*)(vr + (i << 2));
                    fma2(accA[2*i],   ppA, vv.x);
                    fma2(accA[2*i+1], ppA, vv.y);
                    fma2(accB[2*i],   ppB, vv.x);
                    fma2(accB[2*i+1], ppB, vv.y);
                }
            }
        }
        __syncthreads();
    }

    const int pidxA = c * ROWS + growA;
    const int pidxB = c * ROWS + growB;
    if (h == 0) {
        g_m[pidxA] = mA; g_l[pidxA] = lA;
        g_m[pidxB] = mB; g_l[pidxB] = lB;
    }
    ulonglong2* oa = (ulonglong2*)&g_acc[(size_t)pidxA * Hh + h * 32];
    ulonglong2* ob = (ulonglong2*)&g_acc[(size_t)pidxB * Hh + h * 32];
#pragma unroll
    for (int i = 0; i < 8; i++) {
        oa[i] = make_ulonglong2(accA[2*i], accA[2*i+1]);
        ob[i] = make_ulonglong2(accB[2*i], accB[2*i+1]);
    }
}

// ---------------------------------------------------------------------------
// Combine: merge <=16 chunk partials per row.
// ---------------------------------------------------------------------------
__global__ __launch_bounds__(256) void combine_kernel(float* __restrict__ out)
{
    const int t   = blockIdx.x * blockDim.x + threadIdx.x;
    const int row = t >> 4;
    const int d4  = t & 15;
    const int ll  = row & (Ls - 1);
    const int nch = (ll >> 8) + 1;

    float M = -INFINITY;
#pragma unroll 4
    for (int cc = 0; cc < nch; cc++)
        M = fmaxf(M, g_m[cc * ROWS + row]);

    float  Lt = 0.f;
    float4 o  = make_float4(0.f, 0.f, 0.f, 0.f);
#pragma unroll 4
    for (int cc = 0; cc < nch; cc++) {
        const float w = __expf(g_m[cc * ROWS + row] - M);
        Lt += w * g_l[cc * ROWS + row];
        float4 a = *(const float4*)&g_acc[((size_t)cc * ROWS + row) * Hh + (d4 << 2)];
        o.x = fmaf(w, a.x, o.x); o.y = fmaf(w, a.y, o.y);
        o.z = fmaf(w, a.z, o.z); o.w = fmaf(w, a.w, o.w);
    }
    const float inv = 1.f / Lt;
    o.x *= inv; o.y *= inv; o.z *= inv; o.w *= inv;
    *(float4*)&out[(size_t)row * Hh + (d4 << 2)] = o;
}

// ---------------------------------------------------------------------------
extern "C" void kernel_launch(void* const* d_in, const int* in_sizes, int n_in,
                              void* d_out, int out_size)
{
    const float* x  = (const float*)d_in[0];
    const float* Wq = (const float*)d_in[1];
    const float* Wk = (const float*)d_in[2];
    const float* Wv = (const float*)d_in[3];
    float* out = (float*)d_out;

    proj_kernel<<<ROWS / 64, 128>>>(x, Wq, Wk, Wv);

    dim3 ag(Ls / 64, NCH, Bb);
    attnA_kernel<<<ag, 64>>>();

    combine_kernel<<<(ROWS * 16) / 256, 256>>>(out);
}

// round 11
// speedup vs baseline: 2.6275x; 1.1869x over previous
#include <cuda_runtime.h>
#include <cuda_bf16.h>
#include <math.h>
#include <stdint.h>

#define Bb   4
#define Ls   4096
#define Dd   1024
#define Hh   64
#define ROWS (Bb*Ls)      // 16384
#define KCH  256
#define NCH  (Ls/KCH)     // 16

typedef unsigned long long u64;

__device__ float g_q  [ROWS*Hh];
__device__ float g_k  [ROWS*Hh];
__device__ float g_v  [ROWS*Hh];
__device__ float g_m  [NCH*ROWS];
__device__ float g_l  [NCH*ROWS];
__device__ float g_acc[(size_t)NCH*ROWS*Hh];
__device__ __nv_bfloat16 g_wh[192*Dd];   // W^T hi, [n=0..191][k]
__device__ __nv_bfloat16 g_wl[192*Dd];   // W^T lo

// ---- packed f32x2 helpers (attention) --------------------------------------
__device__ __forceinline__ void fma2(u64& d, u64 a, u64 b) {
    asm("fma.rn.f32x2 %0, %1, %2, %0;" : "+l"(d) : "l"(a), "l"(b));
}
__device__ __forceinline__ void mul2(u64& d, u64 a, u64 b) {
    asm("mul.rn.f32x2 %0, %1, %2;" : "=l"(d) : "l"(a), "l"(b));
}
__device__ __forceinline__ u64 pack2(float x, float y) {
    u64 r; asm("mov.b64 %0, {%1, %2};" : "=l"(r) : "f"(x), "f"(y)); return r;
}
__device__ __forceinline__ void unpack2(u64 v, float& x, float& y) {
    asm("mov.b64 {%0, %1}, %2;" : "=f"(x), "=f"(y) : "l"(v));
}

// ---- baseline-sm_103-safe tensor path: ldmatrix + mma.sync -----------------
__device__ __forceinline__ uint32_t smem_u32(const void* p) {
    uint32_t a;
    asm("{ .reg .u64 t; cvta.to.shared.u64 t, %1; cvt.u32.u64 %0, t; }" : "=r"(a) : "l"(p));
    return a;
}
__device__ __forceinline__ void ldmx4(uint32_t r[4], uint32_t addr) {
    asm volatile("ldmatrix.sync.aligned.m8n8.x4.shared.b16 {%0,%1,%2,%3}, [%4];"
                 : "=r"(r[0]), "=r"(r[1]), "=r"(r[2]), "=r"(r[3]) : "r"(addr));
}
__device__ __forceinline__ void mma16816(float d[4], const uint32_t a[4],
                                         uint32_t b0, uint32_t b1) {
    asm volatile(
        "mma.sync.aligned.m16n8k16.row.col.f32.bf16.bf16.f32 "
        "{%0,%1,%2,%3}, {%4,%5,%6,%7}, {%8,%9}, {%0,%1,%2,%3};"
        : "+f"(d[0]), "+f"(d[1]), "+f"(d[2]), "+f"(d[3])
        : "r"(a[0]), "r"(a[1]), "r"(a[2]), "r"(a[3]), "r"(b0), "r"(b1));
}
// physical byte offset in a 128B-row SW128-swizzled tile; j = 16B-column 0..7
__device__ __forceinline__ uint32_t swz_rj(int row, int j) {
    return (uint32_t)(row * 128 + ((j ^ (row & 7)) << 4));
}
__device__ __forceinline__ uint32_t swz_rb(int row, int bytecol) {
    return (uint32_t)(row * 128 + (bytecol ^ ((row & 7) << 4)));
}

// SMEM layout (dynamic, bytes)
#define SM_AH 0
#define SM_AL 16384
#define SM_BH 32768
#define SM_BL 57344
#define SM_TOTAL 81920

// ---------------------------------------------------------------------------
// W prep: split [Wq|Wk|Wv] into bf16 hi/lo, transposed to [n=192][k=1024].
// ---------------------------------------------------------------------------
__global__ __launch_bounds__(256) void prep_w_kernel(
    const float* __restrict__ Wq, const float* __restrict__ Wk,
    const float* __restrict__ Wv)
{
    int idx = blockIdx.x * 256 + threadIdx.x;     // 0 .. 196607
    int n = idx >> 10;
    int k = idx & 1023;
    const float* W = (n < 64) ? Wq : (n < 128) ? Wk : Wv;
    float x = W[(size_t)k * Hh + (n & 63)];
    __nv_bfloat16 h = __float2bfloat16(x);
    __nv_bfloat16 l = __float2bfloat16(x - __bfloat162float(h));
    g_wh[idx] = h;
    g_wl[idx] = l;
}

// ---------------------------------------------------------------------------
// Projection via mma.sync (legacy HMMA, baseline sm_103):
// C[16384,192] = X * [Wq|Wk|Wv], bf16 hi/lo 3-combo split, fp32 accum.
// 128 CTAs (M-tile 128), 256 threads = 8 warps (2 M x 4 N).
// Warp tile: M 64 (4 x m16), N 48 (6 x n8). K-chunks of 64 (4 x k16).
// ---------------------------------------------------------------------------
__global__ __launch_bounds__(256, 1) void proj_mma_kernel(const float* __restrict__ X)
{
    extern __shared__ __align__(1024) char smem[];
    const uint32_t sAh = smem_u32(smem) + SM_AH;
    const uint32_t sAl = smem_u32(smem) + SM_AL;
    const uint32_t sBh = smem_u32(smem) + SM_BH;
    const uint32_t sBl = smem_u32(smem) + SM_BL;

    const int tid  = threadIdx.x;
    const int wid  = tid >> 5;
    const int lane = tid & 31;
    const int r0   = blockIdx.x * 128;
    const int m0   = (wid >> 2) * 64;      // warp M offset (0 or 64)
    const int n0   = (wid & 3) * 48;       // warp N offset (0,48,96,144)
    const int arow = lane & 15;            // ldmatrix row within 16
    const int ahalf = lane >> 4;           // ldmatrix 16B k-half

    float d[4][6][4];
#pragma unroll
    for (int mt = 0; mt < 4; mt++)
#pragma unroll
        for (int nt = 0; nt < 6; nt++)
#pragma unroll
            for (int e = 0; e < 4; e++) d[mt][nt][e] = 0.f;

    for (int ko = 0; ko < 16; ko++) {
        __syncthreads();   // previous chunk's compute done before overwrite
        // ---- stage A: X[128 x 64] fp32 -> bf16 hi/lo, swizzled 128B rows ----
#pragma unroll
        for (int i = 0; i < 8; i++) {
            int f   = tid + i * 256;        // 0..2047 float4s
            int row = f >> 4;
            int c4  = (f & 15) << 2;        // element col
            float4 v = *(const float4*)&X[(size_t)(r0 + row) * Dd + ko * 64 + c4];
            float xs[4] = {v.x, v.y, v.z, v.w};
            __nv_bfloat16 h[4], l[4];
#pragma unroll
            for (int e = 0; e < 4; e++) {
                h[e] = __float2bfloat16(xs[e]);
                l[e] = __float2bfloat16(xs[e] - __bfloat162float(h[e]));
            }
            uint32_t off = swz_rb(row, c4 * 2);
            asm volatile("st.shared.b64 [%0], %1;" :: "r"(sAh + off), "l"(*(u64*)h) : "memory");
            asm volatile("st.shared.b64 [%0], %1;" :: "r"(sAl + off), "l"(*(u64*)l) : "memory");
        }
        // ---- stage B: W^T[192 x 64] bf16 hi/lo from prepped globals ----
#pragma unroll
        for (int i = 0; i < 12; i++) {
            int f   = tid + i * 256;        // 0..3071 u64s
            int row = f >> 4;
            int c4  = (f & 15) << 2;
            u64 hv = *(const u64*)&g_wh[(size_t)row * Dd + ko * 64 + c4];
            u64 lv = *(const u64*)&g_wl[(size_t)row * Dd + ko * 64 + c4];
            uint32_t off = swz_rb(row, c4 * 2);
            asm volatile("st.shared.b64 [%0], %1;" :: "r"(sBh + off), "l"(hv) : "memory");
            asm volatile("st.shared.b64 [%0], %1;" :: "r"(sBl + off), "l"(lv) : "memory");
        }
        __syncthreads();

        // ---- compute: 4 k16 steps ----
#pragma unroll
        for (int s = 0; s < 4; s++) {
            const int j = s * 2 + ahalf;    // 16B column
            uint32_t ah[4][4], al[4][4];
#pragma unroll
            for (int mt = 0; mt < 4; mt++) {
                uint32_t off = swz_rj(m0 + mt * 16 + arow, j);
                ldmx4(ah[mt], sAh + off);
                ldmx4(al[mt], sAl + off);
            }
            uint32_t bh[6][2], bl[6][2];
#pragma unroll
            for (int p = 0; p < 3; p++) {   // pairs of n8 tiles
                uint32_t off = swz_rj(n0 + p * 16 + arow, j);
                uint32_t t[4];
                ldmx4(t, sBh + off);
                bh[2*p][0] = t[0]; bh[2*p][1] = t[2];
                bh[2*p+1][0] = t[1]; bh[2*p+1][1] = t[3];
                ldmx4(t, sBl + off);
                bl[2*p][0] = t[0]; bl[2*p][1] = t[2];
                bl[2*p+1][0] = t[1]; bl[2*p+1][1] = t[3];
            }
#pragma unroll
            for (int mt = 0; mt < 4; mt++)
#pragma unroll
                for (int nt = 0; nt < 6; nt++) {
                    mma16816(d[mt][nt], ah[mt], bh[nt][0], bh[nt][1]);
                    mma16816(d[mt][nt], ah[mt], bl[nt][0], bl[nt][1]);
                    mma16816(d[mt][nt], al[mt], bh[nt][0], bh[nt][1]);
                }
        }
    }

    // ---- epilogue: fragment -> g_q/g_k/g_v (fp32) ----
#pragma unroll
    for (int mt = 0; mt < 4; mt++) {
        const int rbase = r0 + m0 + mt * 16 + (lane >> 2);
#pragma unroll
        for (int nt = 0; nt < 6; nt++) {
            const int cb  = n0 + nt * 8;                 // tile col base (never straddles 64)
            float* dst    = (cb < 64) ? g_q : (cb < 128) ? g_k : g_v;
            const int lc  = (cb & 63) + ((lane & 3) << 1);
            *(float2*)&dst[(size_t)rbase * Hh + lc]       = make_float2(d[mt][nt][0], d[mt][nt][1]);
            *(float2*)&dst[(size_t)(rbase + 8) * Hh + lc] = make_float2(d[mt][nt][2], d[mt][nt][3]);
        }
    }
}

// ---------------------------------------------------------------------------
// Attention pass A (unchanged): qtile 64, chunk 256, d-split query pairs.
// ---------------------------------------------------------------------------
__global__ __launch_bounds__(64) void attnA_kernel()
{
    __shared__ u64 KsU[64 * 34];
    __shared__ u64 VsU[64 * 34];

    const int qtile = blockIdx.x;
    const int c     = blockIdx.y;
    const int b     = blockIdx.z;
    const int q0    = qtile << 6;
    const int cbase = c << 8;
    if (cbase > q0) return;

    const int tid = threadIdx.x;
    const int u   = tid >> 1;
    const int h   = tid & 1;
    const int qA  = (u << 1);
    const int qB  = qA + 1;
    const int growA = b * Ls + q0 + qA;
    const int growB = growA + 1;

    u64 qpA[16], qpB[16];
    {
        const u64 sc = pack2(0.125f, 0.125f);
        const ulonglong2* pa = (const ulonglong2*)&g_q[(size_t)growA * Hh + h * 32];
        const ulonglong2* pb = (const ulonglong2*)&g_q[(size_t)growB * Hh + h * 32];
#pragma unroll
        for (int i = 0; i < 8; i++) {
            ulonglong2 va = pa[i], vb = pb[i];
            mul2(qpA[2*i],   va.x, sc); mul2(qpA[2*i+1], va.y, sc);
            mul2(qpB[2*i],   vb.x, sc); mul2(qpB[2*i+1], vb.y, sc);
        }
    }

    u64 accA[16], accB[16];
#pragma unroll
    for (int i = 0; i < 16; i++) { accA[i] = 0ULL; accB[i] = 0ULL; }
    float mA = -1e30f, mB = -1e30f, lA = 0.f, lB = 0.f;

    const int cdiag  = q0 >> 8;
    const int ntiles = (c < cdiag) ? 4 : (((q0 - cbase) >> 6) + 1);
    const float* kb = g_k + (size_t)(b * Ls) * Hh;
    const float* vb = g_v + (size_t)(b * Ls) * Hh;

    for (int kt = 0; kt < ntiles; kt++) {
        const int kstart = cbase + (kt << 6);
#pragma unroll
        for (int i = 0; i < 16; i++) {
            int f   = tid + i * 64;
            int row = f >> 4;
            int j   = f & 15;
            int di  = row * 34 + ((j & 7) << 2) + ((j >> 3) << 1);
            const float4 kv4 = *(const float4*)&kb[(size_t)(kstart + row) * Hh + (j << 2)];
            const float4 vv4 = *(const float4*)&vb[(size_t)(kstart + row) * Hh + (j << 2)];
            *(float4*)&KsU[di] = kv4;
            *(float4*)&VsU[di] = vv4;
        }
        __syncthreads();

        const bool diag = (kstart == q0);

#pragma unroll
        for (int g = 0; g < 4; g++) {
            float sA[16], sB[16];
#pragma unroll
            for (int j = 0; j < 16; j++) {
                const int key = (g << 4) + j;
                const u64* kr = &KsU[key * 34 + (h << 1)];
                u64 a0 = 0ULL, a1 = 0ULL, b0 = 0ULL, b1 = 0ULL;
#pragma unroll
                for (int i = 0; i < 8; i++) {
                    ulonglong2 kv = *(const ulonglong2*)(kr + (i << 2));
                    fma2(a0, qpA[2*i],   kv.x);
                    fma2(a1, qpA[2*i+1], kv.y);
                    fma2(b0, qpB[2*i],   kv.x);
                    fma2(b1, qpB[2*i+1], kv.y);
                }
                float x0, x1, x2, x3, y0, y1, y2, y3;
                unpack2(a0, x0, x1); unpack2(a1, x2, x3);
                unpack2(b0, y0, y1); unpack2(b1, y2, y3);
                float ra = (x0 + x1) + (x2 + x3);
                float rb = (y0 + y1) + (y2 + y3);
                sA[j] = ra + __shfl_xor_sync(0xffffffffu, ra, 1);
                sB[j] = rb + __shfl_xor_sync(0xffffffffu, rb, 1);
            }
            if (diag) {
#pragma unroll
                for (int j = 0; j < 16; j++) {
                    const int key = (g << 4) + j;
                    if (key > qA) sA[j] = -INFINITY;
                    if (key > qB) sB[j] = -INFINITY;
                }
            }
            float tA = sA[0], tB = sB[0];
#pragma unroll
            for (int j = 1; j < 16; j++) { tA = fmaxf(tA, sA[j]); tB = fmaxf(tB, sB[j]); }
            if (fmaxf(tA, tB) == -INFINITY) continue;

            if (tA > mA) {
                const float s = __expf(mA - tA);
                mA = tA; lA *= s;
                const u64 ss = pack2(s, s);
#pragma unroll
                for (int i = 0; i < 16; i++) mul2(accA[i], accA[i], ss);
            }
            if (tB > mB) {
                const float s = __expf(mB - tB);
                mB = tB; lB *= s;
                const u64 ss = pack2(s, s);
#pragma unroll
                for (int i = 0; i < 16; i++) mul2(accB[i], accB[i], ss);
            }
#pragma unroll
            for (int j = 0; j < 16; j++) {
                const int key = (g << 4) + j;
                const float pA = __expf(sA[j] - mA);
                const float pB = __expf(sB[j] - mB);
                lA += pA; lB += pB;
                const u64 ppA = pack2(pA, pA);
                const u64 ppB = pack2(pB, pB);
                const u64* vr = &VsU[key * 34 + (h << 1)];
#pragma unroll
                for (int i = 0; i < 8; i++) {
                    ulonglong2 vv = *(const ulonglong2*)(vr + (i << 2));
                    fma2(accA[2*i],   ppA, vv.x);
                    fma2(accA[2*i+1], ppA, vv.y);
                    fma2(accB[2*i],   ppB, vv.x);
                    fma2(accB[2*i+1], ppB, vv.y);
                }
            }
        }
        __syncthreads();
    }

    const int pidxA = c * ROWS + growA;
    const int pidxB = c * ROWS + growB;
    if (h == 0) {
        g_m[pidxA] = mA; g_l[pidxA] = lA;
        g_m[pidxB] = mB; g_l[pidxB] = lB;
    }
    ulonglong2* oa = (ulonglong2*)&g_acc[(size_t)pidxA * Hh + h * 32];
    ulonglong2* ob = (ulonglong2*)&g_acc[(size_t)pidxB * Hh + h * 32];
#pragma unroll
    for (int i = 0; i < 8; i++) {
        oa[i] = make_ulonglong2(accA[2*i], accA[2*i+1]);
        ob[i] = make_ulonglong2(accB[2*i], accB[2*i+1]);
    }
}

// ---------------------------------------------------------------------------
__global__ __launch_bounds__(256) void combine_kernel(float* __restrict__ out)
{
    const int t   = blockIdx.x * blockDim.x + threadIdx.x;
    const int row = t >> 4;
    const int d4  = t & 15;
    const int ll  = row & (Ls - 1);
    const int nch = (ll >> 8) + 1;

    float M = -INFINITY;
#pragma unroll 4
    for (int cc = 0; cc < nch; cc++)
        M = fmaxf(M, g_m[cc * ROWS + row]);

    float  Lt = 0.f;
    float4 o  = make_float4(0.f, 0.f, 0.f, 0.f);
#pragma unroll 4
    for (int cc = 0; cc < nch; cc++) {
        const float w = __expf(g_m[cc * ROWS + row] - M);
        Lt += w * g_l[cc * ROWS + row];
        float4 a = *(const float4*)&g_acc[((size_t)cc * ROWS + row) * Hh + (d4 << 2)];
        o.x = fmaf(w, a.x, o.x); o.y = fmaf(w, a.y, o.y);
        o.z = fmaf(w, a.z, o.z); o.w = fmaf(w, a.w, o.w);
    }
    const float inv = 1.f / Lt;
    o.x *= inv; o.y *= inv; o.z *= inv; o.w *= inv;
    *(float4*)&out[(size_t)row * Hh + (d4 << 2)] = o;
}

// ---------------------------------------------------------------------------
extern "C" void kernel_launch(void* const* d_in, const int* in_sizes, int n_in,
                              void* d_out, int out_size)
{
    const float* x  = (const float*)d_in[0];
    const float* Wq = (const float*)d_in[1];
    const float* Wk = (const float*)d_in[2];
    const float* Wv = (const float*)d_in[3];
    float* out = (float*)d_out;

    cudaFuncSetAttribute(proj_mma_kernel,
                         cudaFuncAttributeMaxDynamicSharedMemorySize, SM_TOTAL);

    prep_w_kernel<<<(192 * Dd) / 256, 256>>>(Wq, Wk, Wv);
    proj_mma_kernel<<<ROWS / 128, 256, SM_TOTAL>>>(x);

    dim3 ag(Ls / 64, NCH, Bb);
    attnA_kernel<<<ag, 64>>>();

    combine_kernel<<<(ROWS * 16) / 256, 256>>>(out);
}

// round 12
// speedup vs baseline: 5.3930x; 2.0525x over previous
#include <cuda_runtime.h>
#include <cuda_bf16.h>
#include <math.h>
#include <stdint.h>

#define Bb   4
#define Ls   4096
#define Dd   1024
#define Hh   64
#define ROWS (Bb*Ls)      // 16384
#define KCH  256
#define NCH  (Ls/KCH)     // 16

typedef unsigned long long u64;

__device__ float g_q  [ROWS*Hh];
__device__ float g_k  [ROWS*Hh];
__device__ float g_v  [ROWS*Hh];
__device__ float g_m  [NCH*ROWS];
__device__ float g_l  [NCH*ROWS];
__device__ float g_acc[(size_t)NCH*ROWS*Hh];
__device__ __nv_bfloat16 g_wh[192*Dd];
__device__ __nv_bfloat16 g_wl[192*Dd];
// bf16 hi/lo operand stores for HMMA attention
__device__ __nv_bfloat16 g_qh[ROWS*Hh], g_ql[ROWS*Hh];   // (Q/8) split, [row][dim]
__device__ __nv_bfloat16 g_kh[ROWS*Hh], g_kl[ROWS*Hh];   // K split,    [row][dim]
__device__ __nv_bfloat16 g_vh[ROWS*Hh], g_vl[ROWS*Hh];   // V^T split,  [b][dim][seq]

// ---- helpers ----------------------------------------------------------------
__device__ __forceinline__ uint32_t smem_u32(const void* p) {
    uint32_t a;
    asm("{ .reg .u64 t; cvta.to.shared.u64 t, %1; cvt.u32.u64 %0, t; }" : "=r"(a) : "l"(p));
    return a;
}
__device__ __forceinline__ void ldmx4(uint32_t r[4], uint32_t addr) {
    asm volatile("ldmatrix.sync.aligned.m8n8.x4.shared.b16 {%0,%1,%2,%3}, [%4];"
                 : "=r"(r[0]), "=r"(r[1]), "=r"(r[2]), "=r"(r[3]) : "r"(addr));
}
__device__ __forceinline__ void mma16816(float d[4], const uint32_t a[4],
                                         uint32_t b0, uint32_t b1) {
    asm volatile(
        "mma.sync.aligned.m16n8k16.row.col.f32.bf16.bf16.f32 "
        "{%0,%1,%2,%3}, {%4,%5,%6,%7}, {%8,%9}, {%0,%1,%2,%3};"
        : "+f"(d[0]), "+f"(d[1]), "+f"(d[2]), "+f"(d[3])
        : "r"(a[0]), "r"(a[1]), "r"(a[2]), "r"(a[3]), "r"(b0), "r"(b1));
}
__device__ __forceinline__ uint32_t swz_rj(int row, int j) {
    return (uint32_t)(row * 128 + ((j ^ (row & 7)) << 4));
}
__device__ __forceinline__ uint32_t swz_rb(int row, int bytecol) {
    return (uint32_t)(row * 128 + (bytecol ^ ((row & 7) << 4)));
}
__device__ __forceinline__ uint32_t bfpack(float x, float y) {
    __nv_bfloat162 t = __floats2bfloat162_rn(x, y);
    return *(uint32_t*)&t;
}

// SMEM layout for proj (dynamic, bytes)
#define SM_AH 0
#define SM_AL 16384
#define SM_BH 32768
#define SM_BL 57344
#define SM_TOTAL 81920

// ---------------------------------------------------------------------------
// W prep (unchanged)
// ---------------------------------------------------------------------------
__global__ __launch_bounds__(256) void prep_w_kernel(
    const float* __restrict__ Wq, const float* __restrict__ Wk,
    const float* __restrict__ Wv)
{
    int idx = blockIdx.x * 256 + threadIdx.x;
    int n = idx >> 10;
    int k = idx & 1023;
    const float* W = (n < 64) ? Wq : (n < 128) ? Wk : Wv;
    float x = W[(size_t)k * Hh + (n & 63)];
    __nv_bfloat16 h = __float2bfloat16(x);
    __nv_bfloat16 l = __float2bfloat16(x - __bfloat162float(h));
    g_wh[idx] = h;
    g_wl[idx] = l;
}

// ---------------------------------------------------------------------------
// Projection via mma.sync (unchanged from R11 — proven)
// ---------------------------------------------------------------------------
__global__ __launch_bounds__(256, 1) void proj_mma_kernel(const float* __restrict__ X)
{
    extern __shared__ __align__(1024) char smem[];
    const uint32_t sAh = smem_u32(smem) + SM_AH;
    const uint32_t sAl = smem_u32(smem) + SM_AL;
    const uint32_t sBh = smem_u32(smem) + SM_BH;
    const uint32_t sBl = smem_u32(smem) + SM_BL;

    const int tid  = threadIdx.x;
    const int wid  = tid >> 5;
    const int lane = tid & 31;
    const int r0   = blockIdx.x * 128;
    const int m0   = (wid >> 2) * 64;
    const int n0   = (wid & 3) * 48;
    const int arow = lane & 15;
    const int ahalf = lane >> 4;

    float d[4][6][4];
#pragma unroll
    for (int mt = 0; mt < 4; mt++)
#pragma unroll
        for (int nt = 0; nt < 6; nt++)
#pragma unroll
            for (int e = 0; e < 4; e++) d[mt][nt][e] = 0.f;

    for (int ko = 0; ko < 16; ko++) {
        __syncthreads();
#pragma unroll
        for (int i = 0; i < 8; i++) {
            int f   = tid + i * 256;
            int row = f >> 4;
            int c4  = (f & 15) << 2;
            float4 v = *(const float4*)&X[(size_t)(r0 + row) * Dd + ko * 64 + c4];
            float xs[4] = {v.x, v.y, v.z, v.w};
            __nv_bfloat16 h[4], l[4];
#pragma unroll
            for (int e = 0; e < 4; e++) {
                h[e] = __float2bfloat16(xs[e]);
                l[e] = __float2bfloat16(xs[e] - __bfloat162float(h[e]));
            }
            uint32_t off = swz_rb(row, c4 * 2);
            asm volatile("st.shared.b64 [%0], %1;" :: "r"(sAh + off), "l"(*(u64*)h) : "memory");
            asm volatile("st.shared.b64 [%0], %1;" :: "r"(sAl + off), "l"(*(u64*)l) : "memory");
        }
#pragma unroll
        for (int i = 0; i < 12; i++) {
            int f   = tid + i * 256;
            int row = f >> 4;
            int c4  = (f & 15) << 2;
            u64 hv = *(const u64*)&g_wh[(size_t)row * Dd + ko * 64 + c4];
            u64 lv = *(const u64*)&g_wl[(size_t)row * Dd + ko * 64 + c4];
            uint32_t off = swz_rb(row, c4 * 2);
            asm volatile("st.shared.b64 [%0], %1;" :: "r"(sBh + off), "l"(hv) : "memory");
            asm volatile("st.shared.b64 [%0], %1;" :: "r"(sBl + off), "l"(lv) : "memory");
        }
        __syncthreads();

#pragma unroll
        for (int s = 0; s < 4; s++) {
            const int j = s * 2 + ahalf;
            uint32_t ah[4][4], al[4][4];
#pragma unroll
            for (int mt = 0; mt < 4; mt++) {
                uint32_t off = swz_rj(m0 + mt * 16 + arow, j);
                ldmx4(ah[mt], sAh + off);
                ldmx4(al[mt], sAl + off);
            }
            uint32_t bh[6][2], bl[6][2];
#pragma unroll
            for (int p = 0; p < 3; p++) {
                uint32_t off = swz_rj(n0 + p * 16 + arow, j);
                uint32_t t[4];
                ldmx4(t, sBh + off);
                bh[2*p][0] = t[0]; bh[2*p][1] = t[2];
                bh[2*p+1][0] = t[1]; bh[2*p+1][1] = t[3];
                ldmx4(t, sBl + off);
                bl[2*p][0] = t[0]; bl[2*p][1] = t[2];
                bl[2*p+1][0] = t[1]; bl[2*p+1][1] = t[3];
            }
#pragma unroll
            for (int mt = 0; mt < 4; mt++)
#pragma unroll
                for (int nt = 0; nt < 6; nt++) {
                    mma16816(d[mt][nt], ah[mt], bh[nt][0], bh[nt][1]);
                    mma16816(d[mt][nt], ah[mt], bl[nt][0], bl[nt][1]);
                    mma16816(d[mt][nt], al[mt], bh[nt][0], bh[nt][1]);
                }
        }
    }

#pragma unroll
    for (int mt = 0; mt < 4; mt++) {
        const int rbase = r0 + m0 + mt * 16 + (lane >> 2);
#pragma unroll
        for (int nt = 0; nt < 6; nt++) {
            const int cb  = n0 + nt * 8;
            float* dst    = (cb < 64) ? g_q : (cb < 128) ? g_k : g_v;
            const int lc  = (cb & 63) + ((lane & 3) << 1);
            *(float2*)&dst[(size_t)rbase * Hh + lc]       = make_float2(d[mt][nt][0], d[mt][nt][1]);
            *(float2*)&dst[(size_t)(rbase + 8) * Hh + lc] = make_float2(d[mt][nt][2], d[mt][nt][3]);
        }
    }
}

// ---------------------------------------------------------------------------
// Convert Q (prescaled 1/8) and K to bf16 hi/lo.
// ---------------------------------------------------------------------------
__global__ __launch_bounds__(256) void conv_qk_kernel()
{
    int idx = blockIdx.x * 256 + threadIdx.x;   // 0 .. ROWS*Hh-1
    float q = g_q[idx] * 0.125f;
    __nv_bfloat16 qh = __float2bfloat16(q);
    g_qh[idx] = qh;
    g_ql[idx] = __float2bfloat16(q - __bfloat162float(qh));
    float k = g_k[idx];
    __nv_bfloat16 kh = __float2bfloat16(k);
    g_kh[idx] = kh;
    g_kl[idx] = __float2bfloat16(k - __bfloat162float(kh));
}

// ---------------------------------------------------------------------------
// Transpose V to [b][dim][seq] and split bf16 hi/lo. 64x64 tiles.
// ---------------------------------------------------------------------------
__global__ __launch_bounds__(256) void conv_vt_kernel()
{
    __shared__ float ts[64][65];
    const int s0  = blockIdx.x * 64;
    const int b   = blockIdx.z;
    const int tid = threadIdx.x;
#pragma unroll
    for (int i = 0; i < 16; i++) {
        int f = tid + i * 256;          // 0..4095
        int r = f >> 6, d = f & 63;
        ts[r][d] = g_v[(size_t)(b * Ls + s0 + r) * Hh + d];
    }
    __syncthreads();
#pragma unroll
    for (int i = 0; i < 16; i++) {
        int f = tid + i * 256;
        int d = f >> 6, r = f & 63;
        float v = ts[r][d];
        __nv_bfloat16 h = __float2bfloat16(v);
        size_t o = (size_t)(b * Hh + d) * Ls + s0 + r;
        g_vh[o] = h;
        g_vl[o] = __float2bfloat16(v - __bfloat162float(h));
    }
}

// ---------------------------------------------------------------------------
// HMMA flash attention pass: qtile 64, chunk 256, batch. 128 threads, 4 warps.
// Warp owns 16 query rows. S and O in fp32 fragments; P reuses S registers;
// P D-fragment == A-fragment identity for the PV MMA. bf16 hi/lo 3-combo on
// both GEMMs.
// ---------------------------------------------------------------------------
__global__ __launch_bounds__(128) void attnB_kernel()
{
    __shared__ __align__(1024) char sm[32768];
    const uint32_t s0b = smem_u32(sm);
    const uint32_t sKh = s0b, sKl = s0b + 8192, sVh = s0b + 16384, sVl = s0b + 24576;

    const int qtile = blockIdx.x;
    const int c     = blockIdx.y;
    const int b     = blockIdx.z;
    const int q0    = qtile << 6;
    const int cbase = c << 8;
    if (cbase > q0) return;

    const int tid   = threadIdx.x;
    const int wid   = tid >> 5;
    const int lane  = tid & 31;
    const int m0    = wid << 4;          // warp query-row offset (0,16,32,48)
    const int arow  = lane & 15;
    const int ahalf = lane >> 4;
    const int g     = lane >> 2;         // row in group
    const int tig   = lane & 3;

    // ---- stage Q tile (hi->sKh, lo->sKl) and extract A fragments ----
#pragma unroll
    for (int i = 0; i < 8; i++) {
        int f   = tid + i * 128;         // 0..1023 u64s
        int row = f >> 4;
        int c4  = (f & 15) << 2;         // bf16 col
        u64 hv = *(const u64*)&g_qh[(size_t)(b * Ls + q0 + row) * Hh + c4];
        u64 lv = *(const u64*)&g_ql[(size_t)(b * Ls + q0 + row) * Hh + c4];
        uint32_t off = swz_rb(row, c4 * 2);
        asm volatile("st.shared.b64 [%0], %1;" :: "r"(sKh + off), "l"(hv) : "memory");
        asm volatile("st.shared.b64 [%0], %1;" :: "r"(sKl + off), "l"(lv) : "memory");
    }
    __syncthreads();
    uint32_t qh[4][4], ql[4][4];
#pragma unroll
    for (int s = 0; s < 4; s++) {
        int j = 2 * s + ahalf;
        ldmx4(qh[s], sKh + swz_rj(m0 + arow, j));
        ldmx4(ql[s], sKl + swz_rj(m0 + arow, j));
    }
    __syncthreads();

    float O[8][4];
#pragma unroll
    for (int nt = 0; nt < 8; nt++)
#pragma unroll
        for (int e = 0; e < 4; e++) O[nt][e] = 0.f;
    float mr0 = -1e30f, mr1 = -1e30f, l0 = 0.f, l1 = 0.f;

    const int cdiag  = q0 >> 8;
    const int ntiles = (c < cdiag) ? 4 : (((q0 - cbase) >> 6) + 1);

    for (int kt = 0; kt < ntiles; kt++) {
        const int kstart = cbase + (kt << 6);
        // ---- stage K (rows=keys) and V^T (rows=dims) hi/lo ----
#pragma unroll
        for (int i = 0; i < 8; i++) {
            int f   = tid + i * 128;
            int row = f >> 4;
            int c4  = (f & 15) << 2;
            uint32_t off = swz_rb(row, c4 * 2);
            u64 v;
            v = *(const u64*)&g_kh[(size_t)(b * Ls + kstart + row) * Hh + c4];
            asm volatile("st.shared.b64 [%0], %1;" :: "r"(sKh + off), "l"(v) : "memory");
            v = *(const u64*)&g_kl[(size_t)(b * Ls + kstart + row) * Hh + c4];
            asm volatile("st.shared.b64 [%0], %1;" :: "r"(sKl + off), "l"(v) : "memory");
            v = *(const u64*)&g_vh[(size_t)(b * Hh + row) * Ls + kstart + c4];
            asm volatile("st.shared.b64 [%0], %1;" :: "r"(sVh + off), "l"(v) : "memory");
            v = *(const u64*)&g_vl[(size_t)(b * Hh + row) * Ls + kstart + c4];
            asm volatile("st.shared.b64 [%0], %1;" :: "r"(sVl + off), "l"(v) : "memory");
        }
        __syncthreads();

        // ---- S = (Q/8) K^T : 8 n8-tiles of keys ----
        float S[8][4];
#pragma unroll
        for (int nt = 0; nt < 8; nt++)
#pragma unroll
            for (int e = 0; e < 4; e++) S[nt][e] = 0.f;
#pragma unroll
        for (int s = 0; s < 4; s++) {
            int j = 2 * s + ahalf;
#pragma unroll
            for (int p = 0; p < 4; p++) {
                uint32_t th[4], tl[4];
                ldmx4(th, sKh + swz_rj(p * 16 + arow, j));
                ldmx4(tl, sKl + swz_rj(p * 16 + arow, j));
                mma16816(S[2*p],   qh[s], th[0], th[2]);
                mma16816(S[2*p],   qh[s], tl[0], tl[2]);
                mma16816(S[2*p],   ql[s], th[0], th[2]);
                mma16816(S[2*p+1], qh[s], th[1], th[3]);
                mma16816(S[2*p+1], qh[s], tl[1], tl[3]);
                mma16816(S[2*p+1], ql[s], th[1], th[3]);
            }
        }
        // ---- causal mask on the diagonal tile ----
        if (kstart == q0) {
            const int qr0 = m0 + g;
            const int qr1 = qr0 + 8;
#pragma unroll
            for (int nt = 0; nt < 8; nt++) {
                const int kc = nt * 8 + tig * 2;
                if (kc     > qr0) S[nt][0] = -INFINITY;
                if (kc + 1 > qr0) S[nt][1] = -INFINITY;
                if (kc     > qr1) S[nt][2] = -INFINITY;
                if (kc + 1 > qr1) S[nt][3] = -INFINITY;
            }
        }
        // ---- online softmax on fragments ----
        float rm0 = -INFINITY, rm1 = -INFINITY;
#pragma unroll
        for (int nt = 0; nt < 8; nt++) {
            rm0 = fmaxf(rm0, fmaxf(S[nt][0], S[nt][1]));
            rm1 = fmaxf(rm1, fmaxf(S[nt][2], S[nt][3]));
        }
        rm0 = fmaxf(rm0, __shfl_xor_sync(0xffffffffu, rm0, 1));
        rm0 = fmaxf(rm0, __shfl_xor_sync(0xffffffffu, rm0, 2));
        rm1 = fmaxf(rm1, __shfl_xor_sync(0xffffffffu, rm1, 1));
        rm1 = fmaxf(rm1, __shfl_xor_sync(0xffffffffu, rm1, 2));
        const float mn0 = fmaxf(mr0, rm0);
        const float mn1 = fmaxf(mr1, rm1);
        const float sc0 = __expf(mr0 - mn0);
        const float sc1 = __expf(mr1 - mn1);
        mr0 = mn0; mr1 = mn1;
        l0 *= sc0; l1 *= sc1;
#pragma unroll
        for (int nt = 0; nt < 8; nt++) {
            O[nt][0] *= sc0; O[nt][1] *= sc0;
            O[nt][2] *= sc1; O[nt][3] *= sc1;
        }
#pragma unroll
        for (int nt = 0; nt < 8; nt++) {
            float p0 = __expf(S[nt][0] - mr0);
            float p1 = __expf(S[nt][1] - mr0);
            float p2 = __expf(S[nt][2] - mr1);
            float p3 = __expf(S[nt][3] - mr1);
            l0 += p0 + p1; l1 += p2 + p3;
            S[nt][0] = p0; S[nt][1] = p1; S[nt][2] = p2; S[nt][3] = p3;
        }
        // ---- O += P V : P D-frag -> A-frag identity; B from V^T ----
#pragma unroll
        for (int t = 0; t < 4; t++) {
            uint32_t ph[4], pl[4];
            {
                uint32_t h;
                h = bfpack(S[2*t][0], S[2*t][1]);  ph[0] = h;
                pl[0] = bfpack(S[2*t][0] - __bfloat162float(((__nv_bfloat162*)&h)->x),
                               S[2*t][1] - __bfloat162float(((__nv_bfloat162*)&h)->y));
                h = bfpack(S[2*t][2], S[2*t][3]);  ph[1] = h;
                pl[1] = bfpack(S[2*t][2] - __bfloat162float(((__nv_bfloat162*)&h)->x),
                               S[2*t][3] - __bfloat162float(((__nv_bfloat162*)&h)->y));
                h = bfpack(S[2*t+1][0], S[2*t+1][1]); ph[2] = h;
                pl[2] = bfpack(S[2*t+1][0] - __bfloat162float(((__nv_bfloat162*)&h)->x),
                               S[2*t+1][1] - __bfloat162float(((__nv_bfloat162*)&h)->y));
                h = bfpack(S[2*t+1][2], S[2*t+1][3]); ph[3] = h;
                pl[3] = bfpack(S[2*t+1][2] - __bfloat162float(((__nv_bfloat162*)&h)->x),
                               S[2*t+1][3] - __bfloat162float(((__nv_bfloat162*)&h)->y));
            }
            int j = 2 * t + ahalf;
#pragma unroll
            for (int p = 0; p < 4; p++) {
                uint32_t th[4], tl[4];
                ldmx4(th, sVh + swz_rj(p * 16 + arow, j));
                ldmx4(tl, sVl + swz_rj(p * 16 + arow, j));
                mma16816(O[2*p],   ph, th[0], th[2]);
                mma16816(O[2*p],   ph, tl[0], tl[2]);
                mma16816(O[2*p],   pl, th[0], th[2]);
                mma16816(O[2*p+1], ph, th[1], th[3]);
                mma16816(O[2*p+1], ph, tl[1], tl[3]);
                mma16816(O[2*p+1], pl, th[1], th[3]);
            }
        }
        __syncthreads();
    }

    // ---- finalize row sums across the quad and write partials ----
    l0 += __shfl_xor_sync(0xffffffffu, l0, 1);
    l0 += __shfl_xor_sync(0xffffffffu, l0, 2);
    l1 += __shfl_xor_sync(0xffffffffu, l1, 1);
    l1 += __shfl_xor_sync(0xffffffffu, l1, 2);

    const int grow0 = b * Ls + q0 + m0 + g;
    const int grow1 = grow0 + 8;
    const int pidx0 = c * ROWS + grow0;
    const int pidx1 = c * ROWS + grow1;
    if (tig == 0) {
        g_m[pidx0] = mr0; g_l[pidx0] = l0;
        g_m[pidx1] = mr1; g_l[pidx1] = l1;
    }
#pragma unroll
    for (int nt = 0; nt < 8; nt++) {
        const int col = nt * 8 + tig * 2;
        *(float2*)&g_acc[(size_t)pidx0 * Hh + col] = make_float2(O[nt][0], O[nt][1]);
        *(float2*)&g_acc[(size_t)pidx1 * Hh + col] = make_float2(O[nt][2], O[nt][3]);
    }
}

// ---------------------------------------------------------------------------
__global__ __launch_bounds__(256) void combine_kernel(float* __restrict__ out)
{
    const int t   = blockIdx.x * blockDim.x + threadIdx.x;
    const int row = t >> 4;
    const int d4  = t & 15;
    const int ll  = row & (Ls - 1);
    const int nch = (ll >> 8) + 1;

    float M = -INFINITY;
#pragma unroll 4
    for (int cc = 0; cc < nch; cc++)
        M = fmaxf(M, g_m[cc * ROWS + row]);

    float  Lt = 0.f;
    float4 o  = make_float4(0.f, 0.f, 0.f, 0.f);
#pragma unroll 4
    for (int cc = 0; cc < nch; cc++) {
        const float w = __expf(g_m[cc * ROWS + row] - M);
        Lt += w * g_l[cc * ROWS + row];
        float4 a = *(const float4*)&g_acc[((size_t)cc * ROWS + row) * Hh + (d4 << 2)];
        o.x = fmaf(w, a.x, o.x); o.y = fmaf(w, a.y, o.y);
        o.z = fmaf(w, a.z, o.z); o.w = fmaf(w, a.w, o.w);
    }
    const float inv = 1.f / Lt;
    o.x *= inv; o.y *= inv; o.z *= inv; o.w *= inv;
    *(float4*)&out[(size_t)row * Hh + (d4 << 2)] = o;
}

// ---------------------------------------------------------------------------
extern "C" void kernel_launch(void* const* d_in, const int* in_sizes, int n_in,
                              void* d_out, int out_size)
{
    const float* x  = (const float*)d_in[0];
    const float* Wq = (const float*)d_in[1];
    const float* Wk = (const float*)d_in[2];
    const float* Wv = (const float*)d_in[3];
    float* out = (float*)d_out;

    cudaFuncSetAttribute(proj_mma_kernel,
                         cudaFuncAttributeMaxDynamicSharedMemorySize, SM_TOTAL);

    prep_w_kernel<<<(192 * Dd) / 256, 256>>>(Wq, Wk, Wv);
    proj_mma_kernel<<<ROWS / 128, 256, SM_TOTAL>>>(x);
    conv_qk_kernel<<<(ROWS * Hh) / 256, 256>>>();
    {
        dim3 vg(Ls / 64, 1, Bb);
        conv_vt_kernel<<<vg, 256>>>();
    }
    dim3 ag(Ls / 64, NCH, Bb);
    attnB_kernel<<<ag, 128>>>();

    combine_kernel<<<(ROWS * 16) / 256, 256>>>(out);
}

// round 13
// speedup vs baseline: 6.2540x; 1.1597x over previous
#include <cuda_runtime.h>
#include <cuda_bf16.h>
#include <math.h>
#include <stdint.h>

#define Bb   4
#define Ls   4096
#define Dd   1024
#define Hh   64
#define ROWS (Bb*Ls)      // 16384
#define KCH  512
#define NCH  (Ls/KCH)     // 8

typedef unsigned long long u64;

// log2(e)/8 folded into Q so scores live in the log2 domain
#define QSCALE 0.18033688011112042f

__device__ float g_v  [ROWS*Hh];
__device__ float g_m  [NCH*ROWS];
__device__ float g_l  [NCH*ROWS];
__device__ float g_acc[(size_t)NCH*ROWS*Hh];
__device__ __nv_bfloat16 g_wh[192*Dd];
__device__ __nv_bfloat16 g_wl[192*Dd];
__device__ __nv_bfloat16 g_qh[ROWS*Hh], g_ql[ROWS*Hh];   // (Q*QSCALE) split, [row][dim]
__device__ __nv_bfloat16 g_kh[ROWS*Hh], g_kl[ROWS*Hh];   // K split,          [row][dim]
__device__ __nv_bfloat16 g_vh[ROWS*Hh], g_vl[ROWS*Hh];   // V^T split,        [b][dim][seq]

// ---- helpers ----------------------------------------------------------------
__device__ __forceinline__ uint32_t smem_u32(const void* p) {
    uint32_t a;
    asm("{ .reg .u64 t; cvta.to.shared.u64 t, %1; cvt.u32.u64 %0, t; }" : "=r"(a) : "l"(p));
    return a;
}
__device__ __forceinline__ void ldmx4(uint32_t r[4], uint32_t addr) {
    asm volatile("ldmatrix.sync.aligned.m8n8.x4.shared.b16 {%0,%1,%2,%3}, [%4];"
                 : "=r"(r[0]), "=r"(r[1]), "=r"(r[2]), "=r"(r[3]) : "r"(addr));
}
__device__ __forceinline__ void mma16816(float d[4], const uint32_t a[4],
                                         uint32_t b0, uint32_t b1) {
    asm volatile(
        "mma.sync.aligned.m16n8k16.row.col.f32.bf16.bf16.f32 "
        "{%0,%1,%2,%3}, {%4,%5,%6,%7}, {%8,%9}, {%0,%1,%2,%3};"
        : "+f"(d[0]), "+f"(d[1]), "+f"(d[2]), "+f"(d[3])
        : "r"(a[0]), "r"(a[1]), "r"(a[2]), "r"(a[3]), "r"(b0), "r"(b1));
}
__device__ __forceinline__ uint32_t swz_rj(int row, int j) {
    return (uint32_t)(row * 128 + ((j ^ (row & 7)) << 4));
}
__device__ __forceinline__ uint32_t swz_rb(int row, int bytecol) {
    return (uint32_t)(row * 128 + (bytecol ^ ((row & 7) << 4)));
}
__device__ __forceinline__ uint32_t bfpack(float x, float y) {
    __nv_bfloat162 t = __floats2bfloat162_rn(x, y);
    return *(uint32_t*)&t;
}
__device__ __forceinline__ float ex2(float x) {
    float r; asm("ex2.approx.ftz.f32 %0, %1;" : "=f"(r) : "f"(x)); return r;
}
#define CPA16(dst, src) asm volatile("cp.async.cg.shared.global [%0], [%1], 16;" :: "r"(dst), "l"(src) : "memory")
#define CPA_COMMIT()    asm volatile("cp.async.commit_group;" ::: "memory")
#define CPA_WAIT(n)     asm volatile("cp.async.wait_group %0;" :: "n"(n) : "memory")

// SMEM layout for proj (dynamic, bytes)
#define SM_AH 0
#define SM_AL 16384
#define SM_BH 32768
#define SM_BL 57344
#define SM_TOTAL 81920
// attnB: 2 x 32KB double buffer (Kh|Kl|Vh|Vl each 8KB)
#define ATT_SMEM 65536

// ---------------------------------------------------------------------------
__global__ __launch_bounds__(256) void prep_w_kernel(
    const float* __restrict__ Wq, const float* __restrict__ Wk,
    const float* __restrict__ Wv)
{
    int idx = blockIdx.x * 256 + threadIdx.x;
    int n = idx >> 10;
    int k = idx & 1023;
    const float* W = (n < 64) ? Wq : (n < 128) ? Wk : Wv;
    float x = W[(size_t)k * Hh + (n & 63)];
    __nv_bfloat16 h = __float2bfloat16(x);
    __nv_bfloat16 l = __float2bfloat16(x - __bfloat162float(h));
    g_wh[idx] = h;
    g_wl[idx] = l;
}

// ---------------------------------------------------------------------------
// Projection via mma.sync; epilogue emits q (scaled, split) / k (split) / v (fp32).
// ---------------------------------------------------------------------------
__global__ __launch_bounds__(256, 1) void proj_mma_kernel(const float* __restrict__ X)
{
    extern __shared__ __align__(1024) char smem[];
    const uint32_t sAh = smem_u32(smem) + SM_AH;
    const uint32_t sAl = smem_u32(smem) + SM_AL;
    const uint32_t sBh = smem_u32(smem) + SM_BH;
    const uint32_t sBl = smem_u32(smem) + SM_BL;

    const int tid  = threadIdx.x;
    const int wid  = tid >> 5;
    const int lane = tid & 31;
    const int r0   = blockIdx.x * 128;
    const int m0   = (wid >> 2) * 64;
    const int n0   = (wid & 3) * 48;
    const int arow = lane & 15;
    const int ahalf = lane >> 4;

    float d[4][6][4];
#pragma unroll
    for (int mt = 0; mt < 4; mt++)
#pragma unroll
        for (int nt = 0; nt < 6; nt++)
#pragma unroll
            for (int e = 0; e < 4; e++) d[mt][nt][e] = 0.f;

    for (int ko = 0; ko < 16; ko++) {
        __syncthreads();
#pragma unroll
        for (int i = 0; i < 8; i++) {
            int f   = tid + i * 256;
            int row = f >> 4;
            int c4  = (f & 15) << 2;
            float4 v = *(const float4*)&X[(size_t)(r0 + row) * Dd + ko * 64 + c4];
            float xs[4] = {v.x, v.y, v.z, v.w};
            __nv_bfloat16 h[4], l[4];
#pragma unroll
            for (int e = 0; e < 4; e++) {
                h[e] = __float2bfloat16(xs[e]);
                l[e] = __float2bfloat16(xs[e] - __bfloat162float(h[e]));
            }
            uint32_t off = swz_rb(row, c4 * 2);
            asm volatile("st.shared.b64 [%0], %1;" :: "r"(sAh + off), "l"(*(u64*)h) : "memory");
            asm volatile("st.shared.b64 [%0], %1;" :: "r"(sAl + off), "l"(*(u64*)l) : "memory");
        }
#pragma unroll
        for (int i = 0; i < 12; i++) {
            int f   = tid + i * 256;
            int row = f >> 4;
            int c4  = (f & 15) << 2;
            u64 hv = *(const u64*)&g_wh[(size_t)row * Dd + ko * 64 + c4];
            u64 lv = *(const u64*)&g_wl[(size_t)row * Dd + ko * 64 + c4];
            uint32_t off = swz_rb(row, c4 * 2);
            asm volatile("st.shared.b64 [%0], %1;" :: "r"(sBh + off), "l"(hv) : "memory");
            asm volatile("st.shared.b64 [%0], %1;" :: "r"(sBl + off), "l"(lv) : "memory");
        }
        __syncthreads();

#pragma unroll
        for (int s = 0; s < 4; s++) {
            const int j = s * 2 + ahalf;
            uint32_t ah[4][4], al[4][4];
#pragma unroll
            for (int mt = 0; mt < 4; mt++) {
                uint32_t off = swz_rj(m0 + mt * 16 + arow, j);
                ldmx4(ah[mt], sAh + off);
                ldmx4(al[mt], sAl + off);
            }
            uint32_t bh[6][2], bl[6][2];
#pragma unroll
            for (int p = 0; p < 3; p++) {
                uint32_t off = swz_rj(n0 + p * 16 + arow, j);
                uint32_t t[4];
                ldmx4(t, sBh + off);
                bh[2*p][0] = t[0]; bh[2*p][1] = t[2];
                bh[2*p+1][0] = t[1]; bh[2*p+1][1] = t[3];
                ldmx4(t, sBl + off);
                bl[2*p][0] = t[0]; bl[2*p][1] = t[2];
                bl[2*p+1][0] = t[1]; bl[2*p+1][1] = t[3];
            }
#pragma unroll
            for (int mt = 0; mt < 4; mt++)
#pragma unroll
                for (int nt = 0; nt < 6; nt++) {
                    mma16816(d[mt][nt], ah[mt], bh[nt][0], bh[nt][1]);
                    mma16816(d[mt][nt], ah[mt], bl[nt][0], bl[nt][1]);
                    mma16816(d[mt][nt], al[mt], bh[nt][0], bh[nt][1]);
                }
        }
    }

    // Epilogue: q -> g_qh/g_ql (scaled), k -> g_kh/g_kl, v -> g_v fp32.
#pragma unroll
    for (int mt = 0; mt < 4; mt++) {
        const int rb0 = r0 + m0 + mt * 16 + (lane >> 2);
#pragma unroll
        for (int nt = 0; nt < 6; nt++) {
            const int cb = n0 + nt * 8;
            const int lc = (cb & 63) + ((lane & 3) << 1);
#pragma unroll
            for (int half = 0; half < 2; half++) {
                const size_t row = (size_t)(rb0 + half * 8);
                float v0 = d[mt][nt][2*half], v1 = d[mt][nt][2*half + 1];
                if (cb < 64) {
                    v0 *= QSCALE; v1 *= QSCALE;
                    uint32_t h = bfpack(v0, v1);
                    uint32_t l = bfpack(v0 - __bfloat162float(((__nv_bfloat162*)&h)->x),
                                        v1 - __bfloat162float(((__nv_bfloat162*)&h)->y));
                    *(uint32_t*)&g_qh[row * Hh + lc] = h;
                    *(uint32_t*)&g_ql[row * Hh + lc] = l;
                } else if (cb < 128) {
                    uint32_t h = bfpack(v0, v1);
                    uint32_t l = bfpack(v0 - __bfloat162float(((__nv_bfloat162*)&h)->x),
                                        v1 - __bfloat162float(((__nv_bfloat162*)&h)->y));
                    *(uint32_t*)&g_kh[row * Hh + lc] = h;
                    *(uint32_t*)&g_kl[row * Hh + lc] = l;
                } else {
                    *(float2*)&g_v[row * Hh + lc] = make_float2(v0, v1);
                }
            }
        }
    }
}

// ---------------------------------------------------------------------------
// Transpose V to [b][dim][seq] and split bf16 hi/lo.
// ---------------------------------------------------------------------------
__global__ __launch_bounds__(256) void conv_vt_kernel()
{
    __shared__ float ts[64][65];
    const int s0  = blockIdx.x * 64;
    const int b   = blockIdx.z;
    const int tid = threadIdx.x;
#pragma unroll
    for (int i = 0; i < 16; i++) {
        int f = tid + i * 256;
        int r = f >> 6, d = f & 63;
        ts[r][d] = g_v[(size_t)(b * Ls + s0 + r) * Hh + d];
    }
    __syncthreads();
#pragma unroll
    for (int i = 0; i < 16; i++) {
        int f = tid + i * 256;
        int d = f >> 6, r = f & 63;
        float v = ts[r][d];
        __nv_bfloat16 h = __float2bfloat16(v);
        size_t o = (size_t)(b * Hh + d) * Ls + s0 + r;
        g_vh[o] = h;
        g_vl[o] = __float2bfloat16(v - __bfloat162float(h));
    }
}

// ---------------------------------------------------------------------------
// HMMA flash attention: qtile 64, chunk 512, batch. 128 threads, 4 warps.
// cp.async double-buffered K/V staging; log2-domain softmax (ex2).
// ---------------------------------------------------------------------------
__global__ __launch_bounds__(128) void attnB_kernel()
{
    extern __shared__ __align__(1024) char sm[];
    const uint32_t s0b = smem_u32(sm);

    const int qtile = blockIdx.x;
    const int c     = blockIdx.y;
    const int b     = blockIdx.z;
    const int q0    = qtile << 6;
    const int cbase = c << 9;                  // 512-key chunks
    if (cbase > q0) return;

    const int tid   = threadIdx.x;
    const int wid   = tid >> 5;
    const int lane  = tid & 31;
    const int m0    = wid << 4;
    const int arow  = lane & 15;
    const int ahalf = lane >> 4;
    const int g     = lane >> 2;
    const int tig   = lane & 3;

    // ---- stage Q tile in buffer 0, extract A fragments ----
#pragma unroll
    for (int i = 0; i < 8; i++) {
        int f   = tid + i * 128;
        int row = f >> 4;
        int c4  = (f & 15) << 2;
        u64 hv = *(const u64*)&g_qh[(size_t)(b * Ls + q0 + row) * Hh + c4];
        u64 lv = *(const u64*)&g_ql[(size_t)(b * Ls + q0 + row) * Hh + c4];
        uint32_t off = swz_rb(row, c4 * 2);
        asm volatile("st.shared.b64 [%0], %1;" :: "r"(s0b + off), "l"(hv) : "memory");
        asm volatile("st.shared.b64 [%0], %1;" :: "r"(s0b + 8192 + off), "l"(lv) : "memory");
    }
    __syncthreads();
    uint32_t qh[4][4], ql[4][4];
#pragma unroll
    for (int s = 0; s < 4; s++) {
        int j = 2 * s + ahalf;
        ldmx4(qh[s], s0b + swz_rj(m0 + arow, j));
        ldmx4(ql[s], s0b + 8192 + swz_rj(m0 + arow, j));
    }
    __syncthreads();

    float O[8][4];
#pragma unroll
    for (int nt = 0; nt < 8; nt++)
#pragma unroll
        for (int e = 0; e < 4; e++) O[nt][e] = 0.f;
    float mr0 = -1e30f, mr1 = -1e30f, l0 = 0.f, l1 = 0.f;

    const int cdiag  = q0 >> 9;
    const int ntiles = (c < cdiag) ? 8 : (((q0 - cbase) >> 6) + 1);

    // ---- cp.async staging of one 64-key tile into buffer `buf` ----
    auto stage = [&](int buf, int kstart) {
        const uint32_t base = s0b + buf * 32768;
#pragma unroll
        for (int i = 0; i < 4; i++) {
            int f   = tid + i * 128;       // 0..511
            int row = f >> 3;
            int j   = f & 7;               // 16B chunk
            uint32_t off = (uint32_t)(row * 128 + ((j ^ (row & 7)) << 4));
            CPA16(base + off,         (const char*)&g_kh[(size_t)(b * Ls + kstart + row) * Hh + j * 8]);
            CPA16(base + 8192 + off,  (const char*)&g_kl[(size_t)(b * Ls + kstart + row) * Hh + j * 8]);
            CPA16(base + 16384 + off, (const char*)&g_vh[(size_t)(b * Hh + row) * Ls + kstart + j * 8]);
            CPA16(base + 24576 + off, (const char*)&g_vl[(size_t)(b * Hh + row) * Ls + kstart + j * 8]);
        }
    };

    stage(0, cbase);
    CPA_COMMIT();

    int buf = 0;
    for (int kt = 0; kt < ntiles; kt++) {
        const int kstart = cbase + (kt << 6);
        if (kt + 1 < ntiles) { stage(buf ^ 1, kstart + 64); CPA_COMMIT(); CPA_WAIT(1); }
        else                 { CPA_WAIT(0); }
        __syncthreads();

        const uint32_t sKh = s0b + buf * 32768;
        const uint32_t sKl = sKh + 8192;
        const uint32_t sVh = sKh + 16384;
        const uint32_t sVl = sKh + 24576;

        // ---- S = Q' K^T ----
        float S[8][4];
#pragma unroll
        for (int nt = 0; nt < 8; nt++)
#pragma unroll
            for (int e = 0; e < 4; e++) S[nt][e] = 0.f;
#pragma unroll
        for (int s = 0; s < 4; s++) {
            int j = 2 * s + ahalf;
#pragma unroll
            for (int p = 0; p < 4; p++) {
                uint32_t th[4], tl[4];
                ldmx4(th, sKh + swz_rj(p * 16 + arow, j));
                ldmx4(tl, sKl + swz_rj(p * 16 + arow, j));
                mma16816(S[2*p],   qh[s], th[0], th[2]);
                mma16816(S[2*p],   qh[s], tl[0], tl[2]);
                mma16816(S[2*p],   ql[s], th[0], th[2]);
                mma16816(S[2*p+1], qh[s], th[1], th[3]);
                mma16816(S[2*p+1], qh[s], tl[1], tl[3]);
                mma16816(S[2*p+1], ql[s], th[1], th[3]);
            }
        }
        // ---- causal mask on the diagonal tile ----
        if (kstart == q0) {
            const int qr0 = m0 + g;
            const int qr1 = qr0 + 8;
#pragma unroll
            for (int nt = 0; nt < 8; nt++) {
                const int kc = nt * 8 + tig * 2;
                if (kc     > qr0) S[nt][0] = -INFINITY;
                if (kc + 1 > qr0) S[nt][1] = -INFINITY;
                if (kc     > qr1) S[nt][2] = -INFINITY;
                if (kc + 1 > qr1) S[nt][3] = -INFINITY;
            }
        }
        // ---- online softmax (log2 domain) ----
        float rm0 = -INFINITY, rm1 = -INFINITY;
#pragma unroll
        for (int nt = 0; nt < 8; nt++) {
            rm0 = fmaxf(rm0, fmaxf(S[nt][0], S[nt][1]));
            rm1 = fmaxf(rm1, fmaxf(S[nt][2], S[nt][3]));
        }
        rm0 = fmaxf(rm0, __shfl_xor_sync(0xffffffffu, rm0, 1));
        rm0 = fmaxf(rm0, __shfl_xor_sync(0xffffffffu, rm0, 2));
        rm1 = fmaxf(rm1, __shfl_xor_sync(0xffffffffu, rm1, 1));
        rm1 = fmaxf(rm1, __shfl_xor_sync(0xffffffffu, rm1, 2));
        const float mn0 = fmaxf(mr0, rm0);
        const float mn1 = fmaxf(mr1, rm1);
        const float sc0 = ex2(mr0 - mn0);
        const float sc1 = ex2(mr1 - mn1);
        mr0 = mn0; mr1 = mn1;
        l0 *= sc0; l1 *= sc1;
#pragma unroll
        for (int nt = 0; nt < 8; nt++) {
            O[nt][0] *= sc0; O[nt][1] *= sc0;
            O[nt][2] *= sc1; O[nt][3] *= sc1;
        }
#pragma unroll
        for (int nt = 0; nt < 8; nt++) {
            float p0 = ex2(S[nt][0] - mr0);
            float p1 = ex2(S[nt][1] - mr0);
            float p2 = ex2(S[nt][2] - mr1);
            float p3 = ex2(S[nt][3] - mr1);
            l0 += p0 + p1; l1 += p2 + p3;
            S[nt][0] = p0; S[nt][1] = p1; S[nt][2] = p2; S[nt][3] = p3;
        }
        // ---- O += P V ----
#pragma unroll
        for (int t = 0; t < 4; t++) {
            uint32_t ph[4], pl[4];
            {
                uint32_t h;
                h = bfpack(S[2*t][0], S[2*t][1]);  ph[0] = h;
                pl[0] = bfpack(S[2*t][0] - __bfloat162float(((__nv_bfloat162*)&h)->x),
                               S[2*t][1] - __bfloat162float(((__nv_bfloat162*)&h)->y));
                h = bfpack(S[2*t][2], S[2*t][3]);  ph[1] = h;
                pl[1] = bfpack(S[2*t][2] - __bfloat162float(((__nv_bfloat162*)&h)->x),
                               S[2*t][3] - __bfloat162float(((__nv_bfloat162*)&h)->y));
                h = bfpack(S[2*t+1][0], S[2*t+1][1]); ph[2] = h;
                pl[2] = bfpack(S[2*t+1][0] - __bfloat162float(((__nv_bfloat162*)&h)->x),
                               S[2*t+1][1] - __bfloat162float(((__nv_bfloat162*)&h)->y));
                h = bfpack(S[2*t+1][2], S[2*t+1][3]); ph[3] = h;
                pl[3] = bfpack(S[2*t+1][2] - __bfloat162float(((__nv_bfloat162*)&h)->x),
                               S[2*t+1][3] - __bfloat162float(((__nv_bfloat162*)&h)->y));
            }
            int j = 2 * t + ahalf;
#pragma unroll
            for (int p = 0; p < 4; p++) {
                uint32_t th[4], tl[4];
                ldmx4(th, sVh + swz_rj(p * 16 + arow, j));
                ldmx4(tl, sVl + swz_rj(p * 16 + arow, j));
                mma16816(O[2*p],   ph, th[0], th[2]);
                mma16816(O[2*p],   ph, tl[0], tl[2]);
                mma16816(O[2*p],   pl, th[0], th[2]);
                mma16816(O[2*p+1], ph, th[1], th[3]);
                mma16816(O[2*p+1], ph, tl[1], tl[3]);
                mma16816(O[2*p+1], pl, th[1], th[3]);
            }
        }
        __syncthreads();
        buf ^= 1;
    }

    // ---- finalize + write partials ----
    l0 += __shfl_xor_sync(0xffffffffu, l0, 1);
    l0 += __shfl_xor_sync(0xffffffffu, l0, 2);
    l1 += __shfl_xor_sync(0xffffffffu, l1, 1);
    l1 += __shfl_xor_sync(0xffffffffu, l1, 2);

    const int grow0 = b * Ls + q0 + m0 + g;
    const int grow1 = grow0 + 8;
    const int pidx0 = c * ROWS + grow0;
    const int pidx1 = c * ROWS + grow1;
    if (tig == 0) {
        g_m[pidx0] = mr0; g_l[pidx0] = l0;
        g_m[pidx1] = mr1; g_l[pidx1] = l1;
    }
#pragma unroll
    for (int nt = 0; nt < 8; nt++) {
        const int col = nt * 8 + tig * 2;
        *(float2*)&g_acc[(size_t)pidx0 * Hh + col] = make_float2(O[nt][0], O[nt][1]);
        *(float2*)&g_acc[(size_t)pidx1 * Hh + col] = make_float2(O[nt][2], O[nt][3]);
    }
}

// ---------------------------------------------------------------------------
// Combine: merge <=8 chunk partials per row (log2-domain weights).
// ---------------------------------------------------------------------------
__global__ __launch_bounds__(256) void combine_kernel(float* __restrict__ out)
{
    const int t   = blockIdx.x * blockDim.x + threadIdx.x;
    const int row = t >> 4;
    const int d4  = t & 15;
    const int ll  = row & (Ls - 1);
    const int nch = (ll >> 9) + 1;

    float M = -INFINITY;
#pragma unroll 4
    for (int cc = 0; cc < nch; cc++)
        M = fmaxf(M, g_m[cc * ROWS + row]);

    float  Lt = 0.f;
    float4 o  = make_float4(0.f, 0.f, 0.f, 0.f);
#pragma unroll 4
    for (int cc = 0; cc < nch; cc++) {
        const float w = ex2(g_m[cc * ROWS + row] - M);
        Lt += w * g_l[cc * ROWS + row];
        float4 a = *(const float4*)&g_acc[((size_t)cc * ROWS + row) * Hh + (d4 << 2)];
        o.x = fmaf(w, a.x, o.x); o.y = fmaf(w, a.y, o.y);
        o.z = fmaf(w, a.z, o.z); o.w = fmaf(w, a.w, o.w);
    }
    const float inv = 1.f / Lt;
    o.x *= inv; o.y *= inv; o.z *= inv; o.w *= inv;
    *(float4*)&out[(size_t)row * Hh + (d4 << 2)] = o;
}

// ---------------------------------------------------------------------------
extern "C" void kernel_launch(void* const* d_in, const int* in_sizes, int n_in,
                              void* d_out, int out_size)
{
    const float* x  = (const float*)d_in[0];
    const float* Wq = (const float*)d_in[1];
    const float* Wk = (const float*)d_in[2];
    const float* Wv = (const float*)d_in[3];
    float* out = (float*)d_out;

    cudaFuncSetAttribute(proj_mma_kernel,
                         cudaFuncAttributeMaxDynamicSharedMemorySize, SM_TOTAL);
    cudaFuncSetAttribute(attnB_kernel,
                         cudaFuncAttributeMaxDynamicSharedMemorySize, ATT_SMEM);

    prep_w_kernel<<<(192 * Dd) / 256, 256>>>(Wq, Wk, Wv);
    proj_mma_kernel<<<ROWS / 128, 256, SM_TOTAL>>>(x);
    {
        dim3 vg(Ls / 64, 1, Bb);
        conv_vt_kernel<<<vg, 256>>>();
    }
    dim3 ag(Ls / 64, NCH, Bb);
    attnB_kernel<<<ag, 128, ATT_SMEM>>>();

    combine_kernel<<<(ROWS * 16) / 256, 256>>>(out);
}